// round 9
// baseline (speedup 1.0000x reference)
#include <cuda_runtime.h>
#include <math.h>
#include <stdint.h>
#include <string.h>

#define PI_F 3.14159265358979323846f
#define RCUTF 5.0f
#define NT 10
#define WARPS 8
#define PPC 16              // pairs per CTA (2 per warp)
#define PERMCAP 51712
#define PCAP 50048
#define MMAX 2176

// ============================================================================
// Host-side exact replication of numpy RandomState(seed).standard_normal(...)
// ============================================================================
struct MT19937 {
    uint32_t mt[624];
    int mti;
    void seed(uint32_t s) {
        mt[0] = s;
        for (int i = 1; i < 624; i++)
            mt[i] = 1812433253u * (mt[i-1] ^ (mt[i-1] >> 30)) + (uint32_t)i;
        mti = 624;
    }
    uint32_t next() {
        if (mti >= 624) {
            for (int i = 0; i < 624; i++) {
                uint32_t y = (mt[i] & 0x80000000u) | (mt[(i+1) % 624] & 0x7fffffffu);
                mt[i] = mt[(i+397) % 624] ^ (y >> 1) ^ ((y & 1u) ? 2567483615u : 0u);
            }
            mti = 0;
        }
        uint32_t y = mt[mti++];
        y ^= y >> 11;
        y ^= (y << 7)  & 2636928640u;
        y ^= (y << 15) & 4022730752u;
        y ^= y >> 18;
        return y;
    }
    double rdouble() {
        uint32_t a = next() >> 5, b = next() >> 6;
        return (a * 67108864.0 + b) / 9007199254740992.0;
    }
};
struct GaussGen {
    MT19937 mt;
    bool has;
    double cached;
    void init(uint32_t s) { mt.seed(s); has = false; cached = 0.0; }
    double next() {
        if (has) { has = false; return cached; }
        double x1, x2, r2;
        do {
            x1 = 2.0 * mt.rdouble() - 1.0;
            x2 = 2.0 * mt.rdouble() - 1.0;
            r2 = x1 * x1 + x2 * x2;
        } while (r2 >= 1.0 || r2 == 0.0);
        double f = sqrt(-2.0 * log(r2) / r2);
        cached = f * x1; has = true;
        return f * x2;
    }
};

struct CGParam { float v[966]; };

static void fill_cg(float* out) {
    int off = 0;
    for (int l1 = 0; l1 < 3; l1++)
        for (int l2 = 0; l2 <= l1; l2++)
            for (int l3 = l1 - l2; l3 <= l1 + l2; l3++) {
                GaussGen g; g.init((uint32_t)(1000 + l1*100 + l2*10 + l3));
                int cnt = (2*l1+1) * (2*l2+1) * (2*l3+1);
                for (int q = 0; q < cnt; q++)
                    out[off++] = (float)g.next();
            }
}

// ============================================================================
// Compile-time index tables
// ============================================================================
struct Tables {
    unsigned char tri_x[21], tri_y[21];
    unsigned char et_combo[124], et_k[124], et_xy[124];
    unsigned char h_xy[36], h_l3[36];
    short cgoff[3][3][5];
    unsigned char om_xy[196], om_l1[196], om_l2[196], om_mn[196];
    short ds_t[196];
    unsigned char ds_xy[196], ds_klo[196], ds_len[196];
    short ds_off[196];
    int n_et, n_combo, m_total;
};

constexpr int trif(int x, int y) {
    int lo = x < y ? x : y, hi = x < y ? y : x;
    return hi * (hi + 1) / 2 + lo;
}

constexpr Tables makeTables() {
    Tables t{};
    for (int x = 0; x < 6; x++)
        for (int y = x; y < 6; y++) {
            t.tri_x[trif(x,y)] = (unsigned char)x;
            t.tri_y[trif(x,y)] = (unsigned char)y;
        }
    const int base[3] = {0, 3, 5};
    const int adim[3] = {3, 2, 1};
    {
        int off = 0;
        for (int l1 = 0; l1 < 3; l1++)
            for (int l2 = 0; l2 <= l1; l2++)
                for (int l3 = l1 - l2; l3 <= l1 + l2; l3++) {
                    t.cgoff[l1][l2][l3] = (short)off;
                    off += (2*l1+1) * (2*l2+1) * (2*l3+1);
                }
    }
    {
        bool seenE[21][25] = {};
        short comboId[21][5] = {};
        for (int a = 0; a < 21; a++)
            for (int b = 0; b < 5; b++) comboId[a][b] = -1;
        int ne = 0, nc = 0;
        for (int l1 = 0; l1 < 3; l1++)
            for (int l2 = 0; l2 <= l1; l2++)
                for (int xa = 0; xa < adim[l1]; xa++)
                    for (int xb = 0; xb < adim[l2]; xb++) {
                        int xy = trif(base[l1] + xa, base[l2] + xb);
                        for (int l3 = l1 - l2; l3 <= l1 + l2; l3++) {
                            if (comboId[xy][l3] < 0) {
                                comboId[xy][l3] = (short)nc;
                                t.h_xy[nc] = (unsigned char)xy;
                                t.h_l3[nc] = (unsigned char)l3;
                                nc++;
                            }
                            for (int ap = 0; ap < 2*l3 + 1; ap++) {
                                int k = l3*l3 + ap;
                                if (!seenE[xy][k]) {
                                    seenE[xy][k] = true;
                                    t.et_combo[ne] = (unsigned char)comboId[xy][l3];
                                    t.et_k[ne]  = (unsigned char)k;
                                    t.et_xy[ne] = (unsigned char)xy;
                                    ne++;
                                }
                            }
                        }
                    }
        t.n_et = ne;    // 121
        t.n_combo = nc; // 35
    }
    for (int r = 0; r < 14; r++)
        for (int c = 0; c < 14; c++) {
            int lr = r < 3 ? 0 : (r < 9 ? 1 : 2);
            int xr = r - (lr == 0 ? 0 : (lr == 1 ? 3 : 9));
            int lc = c < 3 ? 0 : (c < 9 ? 1 : 2);
            int xc = c - (lc == 0 ? 0 : (lc == 1 ? 3 : 9));
            int l1 = 0, l2 = 0, X = 0, Y = 0;
            if (lr >= lc) { l1 = lr; l2 = lc; X = xr; Y = xc; }
            else          { l1 = lc; l2 = lr; X = xc; Y = xr; }
            int N = 2*l2 + 1, A = adim[l1], B = adim[l2];
            int flat = X * (N * B) + Y;
            int b = flat % B; int tmp = flat / B;
            int a = tmp % A; tmp /= A;
            int n2 = tmp % N; int m = tmp / N;
            int idx = r * 14 + c;
            t.om_xy[idx] = (unsigned char)trif(base[l1] + a, base[l2] + b);
            t.om_l1[idx] = (unsigned char)l1;
            t.om_l2[idx] = (unsigned char)l2;
            t.om_mn[idx] = (unsigned char)(m * N + n2);
        }
    {
        const int lens[6] = {25, 15, 9, 5, 3, 1};
        int n = 0;
        int moff = 0;
        for (int li = 0; li < 6; li++)
            for (int tt = 0; tt < 196; tt++) {
                int l1 = t.om_l1[tt], l2 = t.om_l2[tt];
                int klo = (l1 - l2) * (l1 - l2);
                int khi = (l1 + l2 + 1) * (l1 + l2 + 1);
                if (khi - klo == lens[li]) {
                    t.ds_t[n] = (short)tt;
                    t.ds_xy[n] = t.om_xy[tt];
                    t.ds_klo[n] = (unsigned char)klo;
                    t.ds_len[n] = (unsigned char)(khi - klo);
                    t.ds_off[n] = (short)moff;
                    moff += khi - klo;
                    n++;
                }
            }
        t.m_total = moff; // 2116
    }
    return t;
}

__constant__ Tables TBc = makeTables();

// Global scratch
__device__ float Hg[100 * 35 * 16];
__device__ float Mg[MMAX];
__device__ int cntg[100];
__device__ int fillg[100];
__device__ int permg[PERMCAP];
__device__ unsigned char tpg[PCAP];

// ============================================================================
// Setup kernel (grid=100, block=576)
// ============================================================================
__global__ void h_kernel(const float* __restrict__ weight,
                         const float* __restrict__ s_col,
                         const float* __restrict__ p_col,
                         const float* __restrict__ d_col,
                         const __grid_constant__ CGParam cgp)
{
    __shared__ float coll[96];
    int tid = threadIdx.x;
    if (tid < 96) {
        float v;
        if (tid < 48)      v = s_col[tid];
        else if (tid < 80) v = p_col[tid - 48];
        else               v = d_col[tid - 80];
        coll[tid] = v;
    }
    if (tid == 0) cntg[blockIdx.x] = 0;
    {
        int gtid = blockIdx.x * 576 + tid;
        for (int idx = gtid; idx < PERMCAP; idx += 100 * 576)
            permg[idx] = -1;
    }
    if (blockIdx.x == 0 && tid < 196) {
        int e = tid;
        int t  = TBc.ds_t[e];
        int l1 = TBc.om_l1[t], l2 = TBc.om_l2[t], mn = TBc.om_mn[t];
        int klo = TBc.ds_klo[e], len = TBc.ds_len[e], off = TBc.ds_off[e];
        for (int q = 0; q < len; q++) {
            int k = klo + q;
            int l3 = (k < 1) ? 0 : (k < 4) ? 1 : (k < 9) ? 2 : (k < 16) ? 3 : 4;
            int ap = k - l3 * l3;
            Mg[off + q] = cgp.v[TBc.cgoff[l1][l2][l3] + mn * (2 * l3 + 1) + ap];
        }
    }
    __syncthreads();
    if (tid >= 560) return;
    int tp = blockIdx.x;
    int t1 = tp / NT, t2 = tp % NT;
    int combo = tid >> 4, c = tid & 15;
    int xy = TBc.h_xy[combo], l3 = TBc.h_l3[combo];
    int x = TBc.tri_x[xy], y = TBc.tri_y[xy];
    const float* w1 = weight + (size_t)(t1 * NT + t2) * 1280 + l3 * 256;
    const float* w2 = weight + (size_t)(t2 * NT + t1) * 1280 + l3 * 256;
    float acc = 0.f;
    #pragma unroll
    for (int b = 0; b < 16; b++)
        acc += coll[x * 16 + b] * coll[y * 16 + b] * (w1[b * 16 + c] + w2[b * 16 + c]);
    Hg[(tp * 35 + combo) * 16 + c] = acc;
}

// ============================================================================
// Binning
// ============================================================================
__global__ void count_kernel(const int* __restrict__ Z,
                             const int* __restrict__ pairs,
                             const int* __restrict__ aidx, int Pn) {
    __shared__ int loc[100];
    int tid = threadIdx.x;
    if (tid < 100) loc[tid] = 0;
    __syncthreads();
    int p = blockIdx.x * blockDim.x + tid;
    if (p < Pn) {
        int ai = aidx[p];
        int t1 = Z[pairs[2 * ai]];
        int t2 = Z[pairs[2 * ai + 1]];
        int tp = t1 * NT + t2;
        tpg[p] = (unsigned char)tp;
        atomicAdd(&loc[tp], 1);
    }
    __syncthreads();
    if (tid < 100 && loc[tid] > 0) atomicAdd(&cntg[tid], loc[tid]);
}

__global__ void scan_kernel() {
    __shared__ int c_s[100];
    int tid = threadIdx.x;
    if (tid < 100) c_s[tid] = cntg[tid];
    __syncthreads();
    if (tid == 0) {
        int run = 0;
        for (int b = 0; b < 100; b++) {
            int c = c_s[b];
            c_s[b] = run;
            run += (c + PPC - 1) & ~(PPC - 1);   // PPC-aligned bins
        }
    }
    __syncthreads();
    if (tid < 100) fillg[tid] = c_s[tid];
}

__global__ void scatter_kernel(int Pn) {
    __shared__ int loc[100];
    __shared__ int base_s[100];
    int tid = threadIdx.x;
    if (tid < 100) loc[tid] = 0;
    __syncthreads();
    int p = blockIdx.x * blockDim.x + tid;
    int tp = -1, rank = 0;
    if (p < Pn) {
        tp = (int)tpg[p];
        rank = atomicAdd(&loc[tp], 1);
    }
    __syncthreads();
    if (tid < 100)
        base_s[tid] = (loc[tid] > 0) ? atomicAdd(&fillg[tid], loc[tid]) : 0;
    __syncthreads();
    if (p < Pn)
        permg[base_s[tp] + rank] = p;
}

// ============================================================================
// Main kernel: 2 pairs per warp (sequential), 16 pairs per CTA, uniform tp
// Dyn smem/warp: rbf[0,32) gsh[32,112) cinS[112,537) (25x17) Ew[544,1069)
// ============================================================================
#define WSLOT 1072

__global__ void __launch_bounds__(256) op_kernel(
    const float* __restrict__ c0, const float* __restrict__ c1,
    const float* __restrict__ c2, const float* __restrict__ c3,
    const float* __restrict__ c4,
    const float* __restrict__ Rpos, const float* __restrict__ w_rad,
    const int* __restrict__ pairs,
    float* __restrict__ out)
{
    __shared__ __align__(16) float Hs[35 * 17 + 5];
    __shared__ __align__(16) float Mv[MMAX];
    __shared__ unsigned char etc_s[121], etk_s[121], etxy_s[121];
    __shared__ short dst_s[196], dsoff_s[196];
    __shared__ unsigned char dsxy_s[196], dsklo_s[196], dslen_s[196];
    __shared__ int ctaTp;
    extern __shared__ __align__(16) float dyn[];

    int tid = threadIdx.x, w = tid >> 5, lane = tid & 31;
    int base = blockIdx.x * PPC;

    if (tid == 0) {
        int pe0 = permg[base];
        ctaTp = (pe0 >= 0) ? (int)tpg[pe0] : -1;
    }
    for (int idx = tid; idx < TBc.m_total; idx += 256) Mv[idx] = Mg[idx];
    if (tid < 121) {
        etc_s[tid]  = TBc.et_combo[tid];
        etk_s[tid]  = TBc.et_k[tid];
        etxy_s[tid] = TBc.et_xy[tid];
    }
    if (tid < 196) {
        dst_s[tid]   = TBc.ds_t[tid];
        dsoff_s[tid] = TBc.ds_off[tid];
        dsxy_s[tid]  = TBc.ds_xy[tid];
        dsklo_s[tid] = TBc.ds_klo[tid];
        dslen_s[tid] = TBc.ds_len[tid];
    }
    __syncthreads();
    int tpc = ctaTp;
    if (tpc < 0) return;
    {
        const float* Hsrc = Hg + (size_t)tpc * 560;
        for (int idx = tid; idx < 560; idx += 256) {
            int combo = idx >> 4, c = idx & 15;
            Hs[combo * 17 + c] = Hsrc[idx];
        }
    }
    __syncthreads();

    float* Wp   = dyn + w * WSLOT;
    float* rbf  = Wp;
    float* gsh  = Wp + 32;
    float* cinS = Wp + 112;
    float* Ew   = Wp + 544;

    int f = lane & 15, h = lane >> 4;
    const int2* pv = (const int2*)pairs;

    #pragma unroll 1
    for (int rep = 0; rep < 2; rep++) {
        int pe = permg[base + rep * WARPS + w];
        if (pe < 0) continue;

        int2 ij = pv[pe];
        int i = ij.x, j = ij.y;

        float dx = Rpos[3*i+0] - Rpos[3*j+0];
        float dy = Rpos[3*i+1] - Rpos[3*j+1];
        float dz = Rpos[3*i+2] - Rpos[3*j+2];
        float d  = sqrtf(dx*dx + dy*dy + dz*dz);
        float env = (d < RCUTF) ? 0.5f * (cosf(PI_F * d / RCUTF) + 1.0f) : 0.0f;
        rbf[lane] = sinf((float)(lane + 1) * PI_F * d / RCUTF) * env;
        __syncwarp();

        // ---- Phase A ----
        #pragma unroll
        for (int li = 0; li < 3; li++) {
            if (!h || li < 2) {
                int l = h ? li + 3 : li;
                const float* wl = w_rad + l * 512 + f;
                float a0 = 0.f, a1 = 0.f, a2 = 0.f, a3 = 0.f;
                #pragma unroll
                for (int q = 0; q < 8; q++) {
                    a0 = fmaf(rbf[4*q+0], __ldg(wl + (4*q+0)*16), a0);
                    a1 = fmaf(rbf[4*q+1], __ldg(wl + (4*q+1)*16), a1);
                    a2 = fmaf(rbf[4*q+2], __ldg(wl + (4*q+2)*16), a2);
                    a3 = fmaf(rbf[4*q+3], __ldg(wl + (4*q+3)*16), a3);
                }
                gsh[l * 16 + f] = (a0 + a1) + (a2 + a3);
            }
        }
        __syncwarp();

        // ---- Stage cin ----
        {
            const float* clp[5] = {c0, c1, c2, c3, c4};
            #pragma unroll
            for (int l = 0; l < 5; l++) {
                const int nm = 2 * l + 1;
                const float* ci = clp[l] + (size_t)i * 16 * nm;
                const float* cj = clp[l] + (size_t)j * 16 * nm;
                for (int idx = lane; idx < 16 * nm; idx += 32) {
                    int c = idx / nm, m = idx - c * nm;
                    cinS[(l * l + m) * 17 + c] = gsh[l * 16 + c] * (ci[idx] + cj[idx]);
                }
            }
        }
        __syncwarp();

        // ---- Phase C' ----
        for (int e = lane; e < 121; e += 32) {
            int combo = etc_s[e], k = etk_s[e], xy = etxy_s[e];
            const float* Hr = Hs + combo * 17;
            const float* cr = cinS + k * 17;
            float acc = 0.f;
            #pragma unroll
            for (int c = 0; c < 16; c++)
                acc = fmaf(Hr[c], cr[c], acc);
            Ew[xy * 25 + k] = acc;
        }
        __syncwarp();

        // ---- Phase D ----
        float* op = out + (size_t)pe * 196;
        for (int e = lane; e < 196; e += 32) {
            int t = dst_s[e];
            const float* Mr = Mv + dsoff_s[e];
            const float* Er = Ew + dsxy_s[e] * 25 + dsklo_s[e];
            int len = dslen_s[e];
            float acc = 0.f;
            for (int q = 0; q < len; q++)
                acc = fmaf(Mr[q], Er[q], acc);
            op[t] = acc;
        }
        __syncwarp();
    }
}

// ============================================================================
// Launch
// ============================================================================
extern "C" void kernel_launch(void* const* d_in, const int* in_sizes, int n_in,
                              void* d_out, int out_size) {
    const float* c0    = (const float*)d_in[0];
    const float* c1    = (const float*)d_in[1];
    const float* c2    = (const float*)d_in[2];
    const float* c3    = (const float*)d_in[3];
    const float* c4    = (const float*)d_in[4];
    const float* Rpos  = (const float*)d_in[5];
    const float* w_rad = (const float*)d_in[6];
    const float* wgt   = (const float*)d_in[7];
    const float* s_col = (const float*)d_in[8];
    const float* p_col = (const float*)d_in[9];
    const float* d_col = (const float*)d_in[10];
    const int*   Z     = (const int*)d_in[11];
    const int*   pairs = (const int*)d_in[12];
    const int*   aidx  = (const int*)d_in[13];
    float* out = (float*)d_out;

    int Pn = in_sizes[13];

    CGParam cg;
    fill_cg(cg.v);

    h_kernel<<<100, 576>>>(wgt, s_col, p_col, d_col, cg);
    count_kernel<<<(Pn + 255) / 256, 256>>>(Z, pairs, aidx, Pn);
    scan_kernel<<<1, 128>>>();
    scatter_kernel<<<(Pn + 255) / 256, 256>>>(Pn);

    size_t shmem = (size_t)WARPS * WSLOT * sizeof(float);
    cudaFuncSetAttribute(op_kernel, cudaFuncAttributeMaxDynamicSharedMemorySize, (int)shmem);
    int gridMain = (Pn + 100 * PPC + PPC - 1) / PPC;
    op_kernel<<<gridMain, 256, shmem>>>(c0, c1, c2, c3, c4, Rpos, w_rad,
                                        pairs, out);
}

// round 10
// speedup vs baseline: 1.2244x; 1.2244x over previous
#include <cuda_runtime.h>
#include <math.h>
#include <stdint.h>
#include <string.h>

#define PI_F 3.14159265358979323846f
#define RCUTF 5.0f
#define NT 10
#define WARPS 8
#define PERMCAP 50704
#define PCAP 50048
#define MMAX 2176

// ============================================================================
// Host-side exact replication of numpy RandomState(seed).standard_normal(...)
// ============================================================================
struct MT19937 {
    uint32_t mt[624];
    int mti;
    void seed(uint32_t s) {
        mt[0] = s;
        for (int i = 1; i < 624; i++)
            mt[i] = 1812433253u * (mt[i-1] ^ (mt[i-1] >> 30)) + (uint32_t)i;
        mti = 624;
    }
    uint32_t next() {
        if (mti >= 624) {
            for (int i = 0; i < 624; i++) {
                uint32_t y = (mt[i] & 0x80000000u) | (mt[(i+1) % 624] & 0x7fffffffu);
                mt[i] = mt[(i+397) % 624] ^ (y >> 1) ^ ((y & 1u) ? 2567483615u : 0u);
            }
            mti = 0;
        }
        uint32_t y = mt[mti++];
        y ^= y >> 11;
        y ^= (y << 7)  & 2636928640u;
        y ^= (y << 15) & 4022730752u;
        y ^= y >> 18;
        return y;
    }
    double rdouble() {
        uint32_t a = next() >> 5, b = next() >> 6;
        return (a * 67108864.0 + b) / 9007199254740992.0;
    }
};
struct GaussGen {
    MT19937 mt;
    bool has;
    double cached;
    void init(uint32_t s) { mt.seed(s); has = false; cached = 0.0; }
    double next() {
        if (has) { has = false; return cached; }
        double x1, x2, r2;
        do {
            x1 = 2.0 * mt.rdouble() - 1.0;
            x2 = 2.0 * mt.rdouble() - 1.0;
            r2 = x1 * x1 + x2 * x2;
        } while (r2 >= 1.0 || r2 == 0.0);
        double f = sqrt(-2.0 * log(r2) / r2);
        cached = f * x1; has = true;
        return f * x2;
    }
};

struct CGParam { float v[966]; };

static void fill_cg(float* out) {
    int off = 0;
    for (int l1 = 0; l1 < 3; l1++)
        for (int l2 = 0; l2 <= l1; l2++)
            for (int l3 = l1 - l2; l3 <= l1 + l2; l3++) {
                GaussGen g; g.init((uint32_t)(1000 + l1*100 + l2*10 + l3));
                int cnt = (2*l1+1) * (2*l2+1) * (2*l3+1);
                for (int q = 0; q < cnt; q++)
                    out[off++] = (float)g.next();
            }
}

// ============================================================================
// Compile-time index tables
// ============================================================================
struct Tables {
    unsigned char tri_x[21], tri_y[21];
    unsigned char ew_off[21], ew_klo[21];          // packed-E row layout by xy
    unsigned char et_combo[124], et_k[124], et_dst[124];
    unsigned char h_xy[36], h_l3[36];
    short cgoff[3][3][5];
    unsigned char om_xy[196], om_l1[196], om_l2[196], om_mn[196];
    short ds_t[196], ds_off[196];
    unsigned char ds_ew[196], ds_len[196];
    int n_et, n_combo, m_total;
};

constexpr int trif(int x, int y) {
    int lo = x < y ? x : y, hi = x < y ? y : x;
    return hi * (hi + 1) / 2 + lo;
}

constexpr int shellof(int x) { return x < 3 ? 0 : (x < 5 ? 1 : 2); }

constexpr Tables makeTables() {
    Tables t{};
    for (int x = 0; x < 6; x++)
        for (int y = x; y < 6; y++) {
            t.tri_x[trif(x,y)] = (unsigned char)x;   // smaller
            t.tri_y[trif(x,y)] = (unsigned char)y;   // larger
        }
    // packed E layout: for each xy, live k range = [(l1-l2)^2, (l1+l2+1)^2)
    {
        int run = 0;
        for (int xy = 0; xy < 21; xy++) {
            int l2 = shellof(t.tri_x[xy]);
            int l1 = shellof(t.tri_y[xy]);
            if (l2 > l1) { int tmp = l1; l1 = l2; l2 = tmp; }
            int klo = (l1 - l2) * (l1 - l2);
            int khi = (l1 + l2 + 1) * (l1 + l2 + 1);
            t.ew_klo[xy] = (unsigned char)klo;
            t.ew_off[xy] = (unsigned char)run;
            run += khi - klo;
        }
        // run == 121
    }
    const int base[3] = {0, 3, 5};
    const int adim[3] = {3, 2, 1};
    {
        int off = 0;
        for (int l1 = 0; l1 < 3; l1++)
            for (int l2 = 0; l2 <= l1; l2++)
                for (int l3 = l1 - l2; l3 <= l1 + l2; l3++) {
                    t.cgoff[l1][l2][l3] = (short)off;
                    off += (2*l1+1) * (2*l2+1) * (2*l3+1);
                }
    }
    {
        bool seenE[21][25] = {};
        short comboId[21][5] = {};
        for (int a = 0; a < 21; a++)
            for (int b = 0; b < 5; b++) comboId[a][b] = -1;
        int ne = 0, nc = 0;
        for (int l1 = 0; l1 < 3; l1++)
            for (int l2 = 0; l2 <= l1; l2++)
                for (int xa = 0; xa < adim[l1]; xa++)
                    for (int xb = 0; xb < adim[l2]; xb++) {
                        int xy = trif(base[l1] + xa, base[l2] + xb);
                        for (int l3 = l1 - l2; l3 <= l1 + l2; l3++) {
                            if (comboId[xy][l3] < 0) {
                                comboId[xy][l3] = (short)nc;
                                t.h_xy[nc] = (unsigned char)xy;
                                t.h_l3[nc] = (unsigned char)l3;
                                nc++;
                            }
                            for (int ap = 0; ap < 2*l3 + 1; ap++) {
                                int k = l3*l3 + ap;
                                if (!seenE[xy][k]) {
                                    seenE[xy][k] = true;
                                    t.et_combo[ne] = (unsigned char)comboId[xy][l3];
                                    t.et_k[ne]  = (unsigned char)k;
                                    t.et_dst[ne] = (unsigned char)(t.ew_off[xy] + k - t.ew_klo[xy]);
                                    ne++;
                                }
                            }
                        }
                    }
        t.n_et = ne;    // 121
        t.n_combo = nc; // 35
    }
    for (int r = 0; r < 14; r++)
        for (int c = 0; c < 14; c++) {
            int lr = r < 3 ? 0 : (r < 9 ? 1 : 2);
            int xr = r - (lr == 0 ? 0 : (lr == 1 ? 3 : 9));
            int lc = c < 3 ? 0 : (c < 9 ? 1 : 2);
            int xc = c - (lc == 0 ? 0 : (lc == 1 ? 3 : 9));
            int l1 = 0, l2 = 0, X = 0, Y = 0;
            if (lr >= lc) { l1 = lr; l2 = lc; X = xr; Y = xc; }
            else          { l1 = lc; l2 = lr; X = xc; Y = xr; }
            int N = 2*l2 + 1, A = adim[l1], B = adim[l2];
            int flat = X * (N * B) + Y;
            int b = flat % B; int tmp = flat / B;
            int a = tmp % A; tmp /= A;
            int n2 = tmp % N; int m = tmp / N;
            int idx = r * 14 + c;
            t.om_xy[idx] = (unsigned char)trif(base[l1] + a, base[l2] + b);
            t.om_l1[idx] = (unsigned char)l1;
            t.om_l2[idx] = (unsigned char)l2;
            t.om_mn[idx] = (unsigned char)(m * N + n2);
        }
    {
        const int lens[6] = {25, 15, 9, 5, 3, 1};
        int n = 0;
        int moff = 0;
        for (int li = 0; li < 6; li++)
            for (int tt = 0; tt < 196; tt++) {
                int l1 = t.om_l1[tt], l2 = t.om_l2[tt];
                int klo = (l1 - l2) * (l1 - l2);
                int khi = (l1 + l2 + 1) * (l1 + l2 + 1);
                if (khi - klo == lens[li]) {
                    t.ds_t[n] = (short)tt;
                    t.ds_ew[n] = t.ew_off[t.om_xy[tt]];
                    t.ds_len[n] = (unsigned char)(khi - klo);
                    t.ds_off[n] = (short)moff;
                    moff += khi - klo;
                    n++;
                }
            }
        t.m_total = moff; // 2116
    }
    return t;
}

__constant__ Tables TBc = makeTables();

// Global scratch
__device__ float Hg[100 * 35 * 16];
__device__ float Mg[MMAX];
__device__ int cntg[100];
__device__ int fillg[100];
__device__ int permg[PERMCAP];
__device__ unsigned char tpg[PCAP];

// ============================================================================
// Setup kernel (grid=100, block=576)
// ============================================================================
__global__ void h_kernel(const float* __restrict__ weight,
                         const float* __restrict__ s_col,
                         const float* __restrict__ p_col,
                         const float* __restrict__ d_col,
                         const __grid_constant__ CGParam cgp)
{
    __shared__ float coll[96];
    int tid = threadIdx.x;
    if (tid < 96) {
        float v;
        if (tid < 48)      v = s_col[tid];
        else if (tid < 80) v = p_col[tid - 48];
        else               v = d_col[tid - 80];
        coll[tid] = v;
    }
    if (tid == 0) cntg[blockIdx.x] = 0;
    {
        int gtid = blockIdx.x * 576 + tid;
        for (int idx = gtid; idx < PERMCAP; idx += 100 * 576)
            permg[idx] = -1;
    }
    if (blockIdx.x == 0 && tid < 196) {
        int e = tid;
        int t  = TBc.ds_t[e];
        int l1 = TBc.om_l1[t], l2 = TBc.om_l2[t], mn = TBc.om_mn[t];
        int klo = (l1 - l2) * (l1 - l2);
        int len = TBc.ds_len[e], off = TBc.ds_off[e];
        for (int q = 0; q < len; q++) {
            int k = klo + q;
            int l3 = (k < 1) ? 0 : (k < 4) ? 1 : (k < 9) ? 2 : (k < 16) ? 3 : 4;
            int ap = k - l3 * l3;
            Mg[off + q] = cgp.v[TBc.cgoff[l1][l2][l3] + mn * (2 * l3 + 1) + ap];
        }
    }
    __syncthreads();
    if (tid >= 560) return;
    int tp = blockIdx.x;
    int t1 = tp / NT, t2 = tp % NT;
    int combo = tid >> 4, c = tid & 15;
    int xy = TBc.h_xy[combo], l3 = TBc.h_l3[combo];
    int x = TBc.tri_x[xy], y = TBc.tri_y[xy];
    const float* w1 = weight + (size_t)(t1 * NT + t2) * 1280 + l3 * 256;
    const float* w2 = weight + (size_t)(t2 * NT + t1) * 1280 + l3 * 256;
    float acc = 0.f;
    #pragma unroll
    for (int b = 0; b < 16; b++)
        acc += coll[x * 16 + b] * coll[y * 16 + b] * (w1[b * 16 + c] + w2[b * 16 + c]);
    Hg[(tp * 35 + combo) * 16 + c] = acc;
}

// ============================================================================
// Binning
// ============================================================================
__global__ void count_kernel(const int* __restrict__ Z,
                             const int* __restrict__ pairs,
                             const int* __restrict__ aidx, int Pn) {
    __shared__ int loc[100];
    int tid = threadIdx.x;
    if (tid < 100) loc[tid] = 0;
    __syncthreads();
    int p = blockIdx.x * blockDim.x + tid;
    if (p < Pn) {
        int ai = aidx[p];
        int t1 = Z[pairs[2 * ai]];
        int t2 = Z[pairs[2 * ai + 1]];
        int tp = t1 * NT + t2;
        tpg[p] = (unsigned char)tp;
        atomicAdd(&loc[tp], 1);
    }
    __syncthreads();
    if (tid < 100 && loc[tid] > 0) atomicAdd(&cntg[tid], loc[tid]);
}

__global__ void scan_kernel() {
    __shared__ int c_s[100];
    int tid = threadIdx.x;
    if (tid < 100) c_s[tid] = cntg[tid];
    __syncthreads();
    if (tid == 0) {
        int run = 0;
        for (int b = 0; b < 100; b++) {
            int c = c_s[b];
            c_s[b] = run;
            run += (c + 7) & ~7;
        }
    }
    __syncthreads();
    if (tid < 100) fillg[tid] = c_s[tid];
}

__global__ void scatter_kernel(int Pn) {
    __shared__ int loc[100];
    __shared__ int base_s[100];
    int tid = threadIdx.x;
    if (tid < 100) loc[tid] = 0;
    __syncthreads();
    int p = blockIdx.x * blockDim.x + tid;
    int tp = -1, rank = 0;
    if (p < Pn) {
        tp = (int)tpg[p];
        rank = atomicAdd(&loc[tp], 1);
    }
    __syncthreads();
    if (tid < 100)
        base_s[tid] = (loc[tid] > 0) ? atomicAdd(&fillg[tid], loc[tid]) : 0;
    __syncthreads();
    if (p < Pn)
        permg[base_s[tp] + rank] = p;
}

// ============================================================================
// Main kernel: one warp per pair, 8 pairs/CTA, CTA-uniform type-pair.
// Dyn smem/warp (floats): Ewp[0,124) (rbf overlays [0,32) during Phase A)
//                         gsh[124,204)  cinS[204,629) (25 rows stride 17)
// WSLOT = 632 -> 20.2 KB dyn per CTA; 5 CTAs/SM.
// ============================================================================
#define WSLOT 632

__global__ void __launch_bounds__(256, 5) op_kernel(
    const float* __restrict__ c0, const float* __restrict__ c1,
    const float* __restrict__ c2, const float* __restrict__ c3,
    const float* __restrict__ c4,
    const float* __restrict__ Rpos, const float* __restrict__ w_rad,
    const int* __restrict__ pairs,
    float* __restrict__ out)
{
    __shared__ __align__(16) float Hs[35 * 17 + 5];
    __shared__ __align__(16) float Mv[MMAX];
    __shared__ unsigned char etc_s[121], etk_s[121], etd_s[121];
    __shared__ short dst_s[196], dsoff_s[196];
    __shared__ unsigned char dsew_s[196], dslen_s[196];
    __shared__ int ctaTp;
    extern __shared__ __align__(16) float dyn[];

    int tid = threadIdx.x, w = tid >> 5, lane = tid & 31;
    int base = blockIdx.x * WARPS;

    if (tid == 0) {
        int pe0 = permg[base];
        ctaTp = (pe0 >= 0) ? (int)tpg[pe0] : -1;
    }
    for (int idx = tid; idx < TBc.m_total; idx += 256) Mv[idx] = Mg[idx];
    if (tid < 121) {
        etc_s[tid] = TBc.et_combo[tid];
        etk_s[tid] = TBc.et_k[tid];
        etd_s[tid] = TBc.et_dst[tid];
    }
    if (tid < 196) {
        dst_s[tid]   = TBc.ds_t[tid];
        dsoff_s[tid] = TBc.ds_off[tid];
        dsew_s[tid]  = TBc.ds_ew[tid];
        dslen_s[tid] = TBc.ds_len[tid];
    }
    __syncthreads();
    int tpc = ctaTp;
    if (tpc < 0) return;
    {
        const float* Hsrc = Hg + (size_t)tpc * 560;
        for (int idx = tid; idx < 560; idx += 256) {
            int combo = idx >> 4, c = idx & 15;
            Hs[combo * 17 + c] = Hsrc[idx];
        }
    }
    __syncthreads();

    int pe = permg[base + w];
    if (pe < 0) return;

    float* Wp   = dyn + w * WSLOT;
    float* Ewp  = Wp;            // 124 (packed E)
    float* rbf  = Wp;            // overlays Ewp[0,32) during Phase A
    float* gsh  = Wp + 124;      // 80
    float* cinS = Wp + 204;      // 25 rows stride 17

    int i = pairs[2 * pe], j = pairs[2 * pe + 1];

    float dx = Rpos[3*i+0] - Rpos[3*j+0];
    float dy = Rpos[3*i+1] - Rpos[3*j+1];
    float dz = Rpos[3*i+2] - Rpos[3*j+2];
    float d  = sqrtf(dx*dx + dy*dy + dz*dz);
    float env = (d < RCUTF) ? 0.5f * (cosf(PI_F * d / RCUTF) + 1.0f) : 0.0f;
    rbf[lane] = sinf((float)(lane + 1) * PI_F * d / RCUTF) * env;
    __syncwarp();

    int f = lane & 15, h = lane >> 4;

    // ---- Phase A: g[l][f] = sum_k rbf[k] * w_rad[l][k][f] (w_rad via L1) ----
    #pragma unroll
    for (int li = 0; li < 3; li++) {
        if (!h || li < 2) {
            int l = h ? li + 3 : li;
            const float* wl = w_rad + l * 512 + f;
            float a0 = 0.f, a1 = 0.f, a2 = 0.f, a3 = 0.f;
            #pragma unroll
            for (int q = 0; q < 8; q++) {
                a0 = fmaf(rbf[4*q+0], __ldg(wl + (4*q+0)*16), a0);
                a1 = fmaf(rbf[4*q+1], __ldg(wl + (4*q+1)*16), a1);
                a2 = fmaf(rbf[4*q+2], __ldg(wl + (4*q+2)*16), a2);
                a3 = fmaf(rbf[4*q+3], __ldg(wl + (4*q+3)*16), a3);
            }
            gsh[l * 16 + f] = (a0 + a1) + (a2 + a3);
        }
    }
    __syncwarp();

    // ---- Stage cin[k=l^2+m][c] = g[l][c]*(ci+cj), stride 17 ----
    {
        const float* clp[5] = {c0, c1, c2, c3, c4};
        #pragma unroll
        for (int l = 0; l < 5; l++) {
            const int nm = 2 * l + 1;
            const float* ci = clp[l] + (size_t)i * 16 * nm;
            const float* cj = clp[l] + (size_t)j * 16 * nm;
            for (int idx = lane; idx < 16 * nm; idx += 32) {
                int c = idx / nm, m = idx - c * nm;
                cinS[(l * l + m) * 17 + c] = gsh[l * 16 + c] * (ci[idx] + cj[idx]);
            }
        }
    }
    __syncwarp();

    // ---- Phase C': packed E[dst] = sum_c Hs[combo][c] * cin[k][c] ----
    for (int e = lane; e < 121; e += 32) {
        int combo = etc_s[e], k = etk_s[e], dst = etd_s[e];
        const float* Hr = Hs + combo * 17;
        const float* cr = cinS + k * 17;
        float acc = 0.f;
        #pragma unroll
        for (int c = 0; c < 16; c++)
            acc = fmaf(Hr[c], cr[c], acc);
        Ewp[dst] = acc;
    }
    __syncwarp();

    // ---- Phase D: out[t] = sum_q Mv[off+q] * Ewp[ew+q] ----
    float* op = out + (size_t)pe * 196;
    for (int e = lane; e < 196; e += 32) {
        int t = dst_s[e];
        const float* Mr = Mv + dsoff_s[e];
        const float* Er = Ewp + dsew_s[e];
        int len = dslen_s[e];
        float acc = 0.f;
        for (int q = 0; q < len; q++)
            acc = fmaf(Mr[q], Er[q], acc);
        op[t] = acc;
    }
}

// ============================================================================
// Launch
// ============================================================================
extern "C" void kernel_launch(void* const* d_in, const int* in_sizes, int n_in,
                              void* d_out, int out_size) {
    const float* c0    = (const float*)d_in[0];
    const float* c1    = (const float*)d_in[1];
    const float* c2    = (const float*)d_in[2];
    const float* c3    = (const float*)d_in[3];
    const float* c4    = (const float*)d_in[4];
    const float* Rpos  = (const float*)d_in[5];
    const float* w_rad = (const float*)d_in[6];
    const float* wgt   = (const float*)d_in[7];
    const float* s_col = (const float*)d_in[8];
    const float* p_col = (const float*)d_in[9];
    const float* d_col = (const float*)d_in[10];
    const int*   Z     = (const int*)d_in[11];
    const int*   pairs = (const int*)d_in[12];
    const int*   aidx  = (const int*)d_in[13];
    float* out = (float*)d_out;

    int Pn = in_sizes[13];

    CGParam cg;
    fill_cg(cg.v);

    h_kernel<<<100, 576>>>(wgt, s_col, p_col, d_col, cg);
    count_kernel<<<(Pn + 255) / 256, 256>>>(Z, pairs, aidx, Pn);
    scan_kernel<<<1, 128>>>();
    scatter_kernel<<<(Pn + 255) / 256, 256>>>(Pn);

    size_t shmem = (size_t)WARPS * WSLOT * sizeof(float);
    cudaFuncSetAttribute(op_kernel, cudaFuncAttributeMaxDynamicSharedMemorySize, (int)shmem);
    int gridMain = (Pn + 700 + 7) / 8;
    op_kernel<<<gridMain, 256, shmem>>>(c0, c1, c2, c3, c4, Rpos, w_rad,
                                        pairs, out);
}

// round 11
// speedup vs baseline: 1.2508x; 1.0215x over previous
#include <cuda_runtime.h>
#include <math.h>
#include <stdint.h>
#include <string.h>

#define PI_F 3.14159265358979323846f
#define RCUTF 5.0f
#define NT 10
#define WARPS 8
#define PERMCAP 50704
#define PCAP 50048
#define MMAX 2176

// ============================================================================
// Host-side exact replication of numpy RandomState(seed).standard_normal(...)
// ============================================================================
struct MT19937 {
    uint32_t mt[624];
    int mti;
    void seed(uint32_t s) {
        mt[0] = s;
        for (int i = 1; i < 624; i++)
            mt[i] = 1812433253u * (mt[i-1] ^ (mt[i-1] >> 30)) + (uint32_t)i;
        mti = 624;
    }
    uint32_t next() {
        if (mti >= 624) {
            for (int i = 0; i < 624; i++) {
                uint32_t y = (mt[i] & 0x80000000u) | (mt[(i+1) % 624] & 0x7fffffffu);
                mt[i] = mt[(i+397) % 624] ^ (y >> 1) ^ ((y & 1u) ? 2567483615u : 0u);
            }
            mti = 0;
        }
        uint32_t y = mt[mti++];
        y ^= y >> 11;
        y ^= (y << 7)  & 2636928640u;
        y ^= (y << 15) & 4022730752u;
        y ^= y >> 18;
        return y;
    }
    double rdouble() {
        uint32_t a = next() >> 5, b = next() >> 6;
        return (a * 67108864.0 + b) / 9007199254740992.0;
    }
};
struct GaussGen {
    MT19937 mt;
    bool has;
    double cached;
    void init(uint32_t s) { mt.seed(s); has = false; cached = 0.0; }
    double next() {
        if (has) { has = false; return cached; }
        double x1, x2, r2;
        do {
            x1 = 2.0 * mt.rdouble() - 1.0;
            x2 = 2.0 * mt.rdouble() - 1.0;
            r2 = x1 * x1 + x2 * x2;
        } while (r2 >= 1.0 || r2 == 0.0);
        double f = sqrt(-2.0 * log(r2) / r2);
        cached = f * x1; has = true;
        return f * x2;
    }
};

struct CGParam { float v[966]; };

static void fill_cg(float* out) {
    int off = 0;
    for (int l1 = 0; l1 < 3; l1++)
        for (int l2 = 0; l2 <= l1; l2++)
            for (int l3 = l1 - l2; l3 <= l1 + l2; l3++) {
                GaussGen g; g.init((uint32_t)(1000 + l1*100 + l2*10 + l3));
                int cnt = (2*l1+1) * (2*l2+1) * (2*l3+1);
                for (int q = 0; q < cnt; q++)
                    out[off++] = (float)g.next();
            }
}

// ============================================================================
// Compile-time index tables
// ============================================================================
struct Tables {
    unsigned char tri_x[21], tri_y[21];
    unsigned char ew_off[21], ew_klo[21];
    unsigned char et_combo[124], et_k[124], et_dst[124];
    unsigned char h_xy[36], h_l3[36];
    short cgoff[3][3][5];
    unsigned char om_xy[196], om_l1[196], om_l2[196], om_mn[196];
    short ds_t[196], ds_off[196];
    unsigned char ds_ew[196], ds_len[196];
    int n_et, n_combo, m_total;
};

constexpr int trif(int x, int y) {
    int lo = x < y ? x : y, hi = x < y ? y : x;
    return hi * (hi + 1) / 2 + lo;
}

constexpr int shellof(int x) { return x < 3 ? 0 : (x < 5 ? 1 : 2); }

constexpr Tables makeTables() {
    Tables t{};
    for (int x = 0; x < 6; x++)
        for (int y = x; y < 6; y++) {
            t.tri_x[trif(x,y)] = (unsigned char)x;
            t.tri_y[trif(x,y)] = (unsigned char)y;
        }
    {
        int run = 0;
        for (int xy = 0; xy < 21; xy++) {
            int l2 = shellof(t.tri_x[xy]);
            int l1 = shellof(t.tri_y[xy]);
            if (l2 > l1) { int tmp = l1; l1 = l2; l2 = tmp; }
            int klo = (l1 - l2) * (l1 - l2);
            int khi = (l1 + l2 + 1) * (l1 + l2 + 1);
            t.ew_klo[xy] = (unsigned char)klo;
            t.ew_off[xy] = (unsigned char)run;
            run += khi - klo;
        }
    }
    const int base[3] = {0, 3, 5};
    const int adim[3] = {3, 2, 1};
    {
        int off = 0;
        for (int l1 = 0; l1 < 3; l1++)
            for (int l2 = 0; l2 <= l1; l2++)
                for (int l3 = l1 - l2; l3 <= l1 + l2; l3++) {
                    t.cgoff[l1][l2][l3] = (short)off;
                    off += (2*l1+1) * (2*l2+1) * (2*l3+1);
                }
    }
    {
        bool seenE[21][25] = {};
        short comboId[21][5] = {};
        for (int a = 0; a < 21; a++)
            for (int b = 0; b < 5; b++) comboId[a][b] = -1;
        int ne = 0, nc = 0;
        for (int l1 = 0; l1 < 3; l1++)
            for (int l2 = 0; l2 <= l1; l2++)
                for (int xa = 0; xa < adim[l1]; xa++)
                    for (int xb = 0; xb < adim[l2]; xb++) {
                        int xy = trif(base[l1] + xa, base[l2] + xb);
                        for (int l3 = l1 - l2; l3 <= l1 + l2; l3++) {
                            if (comboId[xy][l3] < 0) {
                                comboId[xy][l3] = (short)nc;
                                t.h_xy[nc] = (unsigned char)xy;
                                t.h_l3[nc] = (unsigned char)l3;
                                nc++;
                            }
                            for (int ap = 0; ap < 2*l3 + 1; ap++) {
                                int k = l3*l3 + ap;
                                if (!seenE[xy][k]) {
                                    seenE[xy][k] = true;
                                    t.et_combo[ne] = (unsigned char)comboId[xy][l3];
                                    t.et_k[ne]  = (unsigned char)k;
                                    t.et_dst[ne] = (unsigned char)(t.ew_off[xy] + k - t.ew_klo[xy]);
                                    ne++;
                                }
                            }
                        }
                    }
        t.n_et = ne;
        t.n_combo = nc;
    }
    for (int r = 0; r < 14; r++)
        for (int c = 0; c < 14; c++) {
            int lr = r < 3 ? 0 : (r < 9 ? 1 : 2);
            int xr = r - (lr == 0 ? 0 : (lr == 1 ? 3 : 9));
            int lc = c < 3 ? 0 : (c < 9 ? 1 : 2);
            int xc = c - (lc == 0 ? 0 : (lc == 1 ? 3 : 9));
            int l1 = 0, l2 = 0, X = 0, Y = 0;
            if (lr >= lc) { l1 = lr; l2 = lc; X = xr; Y = xc; }
            else          { l1 = lc; l2 = lr; X = xc; Y = xr; }
            int N = 2*l2 + 1, A = adim[l1], B = adim[l2];
            int flat = X * (N * B) + Y;
            int b = flat % B; int tmp = flat / B;
            int a = tmp % A; tmp /= A;
            int n2 = tmp % N; int m = tmp / N;
            int idx = r * 14 + c;
            t.om_xy[idx] = (unsigned char)trif(base[l1] + a, base[l2] + b);
            t.om_l1[idx] = (unsigned char)l1;
            t.om_l2[idx] = (unsigned char)l2;
            t.om_mn[idx] = (unsigned char)(m * N + n2);
        }
    {
        const int lens[6] = {25, 15, 9, 5, 3, 1};
        int n = 0;
        int moff = 0;
        for (int li = 0; li < 6; li++)
            for (int tt = 0; tt < 196; tt++) {
                int l1 = t.om_l1[tt], l2 = t.om_l2[tt];
                int klo = (l1 - l2) * (l1 - l2);
                int khi = (l1 + l2 + 1) * (l1 + l2 + 1);
                if (khi - klo == lens[li]) {
                    t.ds_t[n] = (short)tt;
                    t.ds_ew[n] = t.ew_off[t.om_xy[tt]];
                    t.ds_len[n] = (unsigned char)(khi - klo);
                    t.ds_off[n] = (short)moff;
                    moff += khi - klo;
                    n++;
                }
            }
        t.m_total = moff;
    }
    return t;
}

__constant__ Tables TBc = makeTables();

// Global scratch
__device__ float Hg[100 * 35 * 16];
__device__ float Mg[MMAX];
__device__ int cntg[100];
__device__ int fillg[100];
__device__ int permg[PERMCAP];
__device__ unsigned char tpg[PCAP];

// ============================================================================
// Setup kernel (grid=100, block=576):
//  - H[tp] for block tp; zero cntg; init permg; block0 builds Mg
//  - computes tpg[p] for its slice of pairs (hides the aidx->pairs->Z chain)
// ============================================================================
__global__ void h_kernel(const float* __restrict__ weight,
                         const float* __restrict__ s_col,
                         const float* __restrict__ p_col,
                         const float* __restrict__ d_col,
                         const int* __restrict__ Z,
                         const int* __restrict__ pairs,
                         const int* __restrict__ aidx, int Pn,
                         const __grid_constant__ CGParam cgp)
{
    __shared__ float coll[96];
    int tid = threadIdx.x;
    if (tid < 96) {
        float v;
        if (tid < 48)      v = s_col[tid];
        else if (tid < 80) v = p_col[tid - 48];
        else               v = d_col[tid - 80];
        coll[tid] = v;
    }
    if (tid == 0) cntg[blockIdx.x] = 0;
    {
        int gtid = blockIdx.x * 576 + tid;
        // tp per pair (57600 threads >= Pn)
        if (gtid < Pn) {
            int ai = aidx[gtid];
            int t1 = Z[pairs[2 * ai]];
            int t2 = Z[pairs[2 * ai + 1]];
            tpg[gtid] = (unsigned char)(t1 * NT + t2);
        }
        for (int idx = gtid; idx < PERMCAP; idx += 100 * 576)
            permg[idx] = -1;
    }
    if (blockIdx.x == 0 && tid < 196) {
        int e = tid;
        int t  = TBc.ds_t[e];
        int l1 = TBc.om_l1[t], l2 = TBc.om_l2[t], mn = TBc.om_mn[t];
        int klo = (l1 - l2) * (l1 - l2);
        int len = TBc.ds_len[e], off = TBc.ds_off[e];
        for (int q = 0; q < len; q++) {
            int k = klo + q;
            int l3 = (k < 1) ? 0 : (k < 4) ? 1 : (k < 9) ? 2 : (k < 16) ? 3 : 4;
            int ap = k - l3 * l3;
            Mg[off + q] = cgp.v[TBc.cgoff[l1][l2][l3] + mn * (2 * l3 + 1) + ap];
        }
    }
    __syncthreads();
    if (tid >= 560) return;
    int tp = blockIdx.x;
    int t1 = tp / NT, t2 = tp % NT;
    int combo = tid >> 4, c = tid & 15;
    int xy = TBc.h_xy[combo], l3 = TBc.h_l3[combo];
    int x = TBc.tri_x[xy], y = TBc.tri_y[xy];
    const float* w1 = weight + (size_t)(t1 * NT + t2) * 1280 + l3 * 256;
    const float* w2 = weight + (size_t)(t2 * NT + t1) * 1280 + l3 * 256;
    float acc = 0.f;
    #pragma unroll
    for (int b = 0; b < 16; b++)
        acc += coll[x * 16 + b] * coll[y * 16 + b] * (w1[b * 16 + c] + w2[b * 16 + c]);
    Hg[(tp * 35 + combo) * 16 + c] = acc;
}

// ============================================================================
// Binning (tpg precomputed in h_kernel)
// ============================================================================
__global__ void count_kernel(int Pn) {
    __shared__ int loc[100];
    int tid = threadIdx.x;
    if (tid < 100) loc[tid] = 0;
    __syncthreads();
    int p = blockIdx.x * blockDim.x + tid;
    if (p < Pn) atomicAdd(&loc[tpg[p]], 1);
    __syncthreads();
    if (tid < 100 && loc[tid] > 0) atomicAdd(&cntg[tid], loc[tid]);
}

__global__ void scan_kernel() {
    __shared__ int c_s[100];
    int tid = threadIdx.x;
    if (tid < 100) c_s[tid] = cntg[tid];
    __syncthreads();
    if (tid == 0) {
        int run = 0;
        for (int b = 0; b < 100; b++) {
            int c = c_s[b];
            c_s[b] = run;
            run += (c + 7) & ~7;
        }
    }
    __syncthreads();
    if (tid < 100) fillg[tid] = c_s[tid];
}

__global__ void scatter_kernel(int Pn) {
    __shared__ int loc[100];
    __shared__ int base_s[100];
    int tid = threadIdx.x;
    if (tid < 100) loc[tid] = 0;
    __syncthreads();
    int p = blockIdx.x * blockDim.x + tid;
    int tp = -1, rank = 0;
    if (p < Pn) {
        tp = (int)tpg[p];
        rank = atomicAdd(&loc[tp], 1);
    }
    __syncthreads();
    if (tid < 100)
        base_s[tid] = (loc[tid] > 0) ? atomicAdd(&fillg[tid], loc[tid]) : 0;
    __syncthreads();
    if (p < Pn)
        permg[base_s[tp] + rank] = p;
}

// ============================================================================
// Main kernel: one warp per pair, 8 pairs/CTA, CTA-uniform type-pair.
// Dyn smem/warp (floats): Ewp[0,124) (rbf overlays [0,32))
//                         gsh[124,204)  cinS[204,629) (25 rows stride 17)
// WSLOT = 632 -> 20.2 KB dyn; target 6 CTAs/SM (regs capped at 42).
// ============================================================================
#define WSLOT 632

__global__ void __launch_bounds__(256, 6) op_kernel(
    const float* __restrict__ c0, const float* __restrict__ c1,
    const float* __restrict__ c2, const float* __restrict__ c3,
    const float* __restrict__ c4,
    const float* __restrict__ Rpos, const float* __restrict__ w_rad,
    const int* __restrict__ pairs,
    float* __restrict__ out)
{
    __shared__ __align__(16) float Hs[35 * 17 + 5];
    __shared__ __align__(16) float Mv[MMAX];
    __shared__ unsigned char etc_s[121], etk_s[121], etd_s[121];
    __shared__ short dst_s[196], dsoff_s[196];
    __shared__ unsigned char dsew_s[196], dslen_s[196];
    __shared__ int ctaTp;
    extern __shared__ __align__(16) float dyn[];

    int tid = threadIdx.x, w = tid >> 5, lane = tid & 31;
    int base = blockIdx.x * WARPS;

    if (tid == 0) {
        int pe0 = permg[base];
        ctaTp = (pe0 >= 0) ? (int)tpg[pe0] : -1;
    }
    for (int idx = tid; idx < TBc.m_total; idx += 256) Mv[idx] = Mg[idx];
    if (tid < 121) {
        etc_s[tid] = TBc.et_combo[tid];
        etk_s[tid] = TBc.et_k[tid];
        etd_s[tid] = TBc.et_dst[tid];
    }
    if (tid < 196) {
        dst_s[tid]   = TBc.ds_t[tid];
        dsoff_s[tid] = TBc.ds_off[tid];
        dsew_s[tid]  = TBc.ds_ew[tid];
        dslen_s[tid] = TBc.ds_len[tid];
    }
    __syncthreads();
    int tpc = ctaTp;
    if (tpc < 0) return;
    {
        const float* Hsrc = Hg + (size_t)tpc * 560;
        for (int idx = tid; idx < 560; idx += 256) {
            int combo = idx >> 4, c = idx & 15;
            Hs[combo * 17 + c] = Hsrc[idx];
        }
    }
    __syncthreads();

    int pe = permg[base + w];
    if (pe < 0) return;

    float* Wp   = dyn + w * WSLOT;
    float* Ewp  = Wp;
    float* rbf  = Wp;
    float* gsh  = Wp + 124;
    float* cinS = Wp + 204;

    int i = pairs[2 * pe], j = pairs[2 * pe + 1];

    float dx = Rpos[3*i+0] - Rpos[3*j+0];
    float dy = Rpos[3*i+1] - Rpos[3*j+1];
    float dz = Rpos[3*i+2] - Rpos[3*j+2];
    float d  = sqrtf(dx*dx + dy*dy + dz*dz);
    float env = (d < RCUTF) ? 0.5f * (cosf(PI_F * d / RCUTF) + 1.0f) : 0.0f;
    rbf[lane] = sinf((float)(lane + 1) * PI_F * d / RCUTF) * env;
    __syncwarp();

    int f = lane & 15, h = lane >> 4;

    // ---- Phase A ----
    #pragma unroll
    for (int li = 0; li < 3; li++) {
        if (!h || li < 2) {
            int l = h ? li + 3 : li;
            const float* wl = w_rad + l * 512 + f;
            float a0 = 0.f, a1 = 0.f, a2 = 0.f, a3 = 0.f;
            #pragma unroll
            for (int q = 0; q < 8; q++) {
                a0 = fmaf(rbf[4*q+0], __ldg(wl + (4*q+0)*16), a0);
                a1 = fmaf(rbf[4*q+1], __ldg(wl + (4*q+1)*16), a1);
                a2 = fmaf(rbf[4*q+2], __ldg(wl + (4*q+2)*16), a2);
                a3 = fmaf(rbf[4*q+3], __ldg(wl + (4*q+3)*16), a3);
            }
            gsh[l * 16 + f] = (a0 + a1) + (a2 + a3);
        }
    }
    __syncwarp();

    // ---- Stage cin ----
    {
        const float* clp[5] = {c0, c1, c2, c3, c4};
        #pragma unroll
        for (int l = 0; l < 5; l++) {
            const int nm = 2 * l + 1;
            const float* ci = clp[l] + (size_t)i * 16 * nm;
            const float* cj = clp[l] + (size_t)j * 16 * nm;
            for (int idx = lane; idx < 16 * nm; idx += 32) {
                int c = idx / nm, m = idx - c * nm;
                cinS[(l * l + m) * 17 + c] = gsh[l * 16 + c] * (ci[idx] + cj[idx]);
            }
        }
    }
    __syncwarp();

    // ---- Phase C' ----
    for (int e = lane; e < 121; e += 32) {
        int combo = etc_s[e], k = etk_s[e], dst = etd_s[e];
        const float* Hr = Hs + combo * 17;
        const float* cr = cinS + k * 17;
        float acc = 0.f;
        #pragma unroll
        for (int c = 0; c < 16; c++)
            acc = fmaf(Hr[c], cr[c], acc);
        Ewp[dst] = acc;
    }
    __syncwarp();

    // ---- Phase D ----
    float* op = out + (size_t)pe * 196;
    for (int e = lane; e < 196; e += 32) {
        int t = dst_s[e];
        const float* Mr = Mv + dsoff_s[e];
        const float* Er = Ewp + dsew_s[e];
        int len = dslen_s[e];
        float acc = 0.f;
        for (int q = 0; q < len; q++)
            acc = fmaf(Mr[q], Er[q], acc);
        op[t] = acc;
    }
}

// ============================================================================
// Launch
// ============================================================================
extern "C" void kernel_launch(void* const* d_in, const int* in_sizes, int n_in,
                              void* d_out, int out_size) {
    const float* c0    = (const float*)d_in[0];
    const float* c1    = (const float*)d_in[1];
    const float* c2    = (const float*)d_in[2];
    const float* c3    = (const float*)d_in[3];
    const float* c4    = (const float*)d_in[4];
    const float* Rpos  = (const float*)d_in[5];
    const float* w_rad = (const float*)d_in[6];
    const float* wgt   = (const float*)d_in[7];
    const float* s_col = (const float*)d_in[8];
    const float* p_col = (const float*)d_in[9];
    const float* d_col = (const float*)d_in[10];
    const int*   Z     = (const int*)d_in[11];
    const int*   pairs = (const int*)d_in[12];
    const int*   aidx  = (const int*)d_in[13];
    float* out = (float*)d_out;

    int Pn = in_sizes[13];

    CGParam cg;
    fill_cg(cg.v);

    h_kernel<<<100, 576>>>(wgt, s_col, p_col, d_col, Z, pairs, aidx, Pn, cg);
    count_kernel<<<(Pn + 255) / 256, 256>>>(Pn);
    scan_kernel<<<1, 128>>>();
    scatter_kernel<<<(Pn + 255) / 256, 256>>>(Pn);

    size_t shmem = (size_t)WARPS * WSLOT * sizeof(float);
    cudaFuncSetAttribute(op_kernel, cudaFuncAttributeMaxDynamicSharedMemorySize, (int)shmem);
    int gridMain = (Pn + 700 + 7) / 8;
    op_kernel<<<gridMain, 256, shmem>>>(c0, c1, c2, c3, c4, Rpos, w_rad,
                                        pairs, out);
}

// round 12
// speedup vs baseline: 1.3206x; 1.0558x over previous
#include <cuda_runtime.h>
#include <math.h>
#include <stdint.h>
#include <string.h>

#define PI_F 3.14159265358979323846f
#define RCUTF 5.0f
#define NT 10
#define WARPS 8
#define PERMCAP 50704
#define PCAP 50048
#define MMAX 2176

// ============================================================================
// Host-side exact replication of numpy RandomState(seed).standard_normal(...)
// ============================================================================
struct MT19937 {
    uint32_t mt[624];
    int mti;
    void seed(uint32_t s) {
        mt[0] = s;
        for (int i = 1; i < 624; i++)
            mt[i] = 1812433253u * (mt[i-1] ^ (mt[i-1] >> 30)) + (uint32_t)i;
        mti = 624;
    }
    uint32_t next() {
        if (mti >= 624) {
            for (int i = 0; i < 624; i++) {
                uint32_t y = (mt[i] & 0x80000000u) | (mt[(i+1) % 624] & 0x7fffffffu);
                mt[i] = mt[(i+397) % 624] ^ (y >> 1) ^ ((y & 1u) ? 2567483615u : 0u);
            }
            mti = 0;
        }
        uint32_t y = mt[mti++];
        y ^= y >> 11;
        y ^= (y << 7)  & 2636928640u;
        y ^= (y << 15) & 4022730752u;
        y ^= y >> 18;
        return y;
    }
    double rdouble() {
        uint32_t a = next() >> 5, b = next() >> 6;
        return (a * 67108864.0 + b) / 9007199254740992.0;
    }
};
struct GaussGen {
    MT19937 mt;
    bool has;
    double cached;
    void init(uint32_t s) { mt.seed(s); has = false; cached = 0.0; }
    double next() {
        if (has) { has = false; return cached; }
        double x1, x2, r2;
        do {
            x1 = 2.0 * mt.rdouble() - 1.0;
            x2 = 2.0 * mt.rdouble() - 1.0;
            r2 = x1 * x1 + x2 * x2;
        } while (r2 >= 1.0 || r2 == 0.0);
        double f = sqrt(-2.0 * log(r2) / r2);
        cached = f * x1; has = true;
        return f * x2;
    }
};

struct CGParam { float v[966]; };

static void fill_cg(float* out) {
    int off = 0;
    for (int l1 = 0; l1 < 3; l1++)
        for (int l2 = 0; l2 <= l1; l2++)
            for (int l3 = l1 - l2; l3 <= l1 + l2; l3++) {
                GaussGen g; g.init((uint32_t)(1000 + l1*100 + l2*10 + l3));
                int cnt = (2*l1+1) * (2*l2+1) * (2*l3+1);
                for (int q = 0; q < cnt; q++)
                    out[off++] = (float)g.next();
            }
}

// ============================================================================
// Compile-time index tables
// ============================================================================
struct Tables {
    unsigned char tri_x[21], tri_y[21];
    unsigned char ew_off[21], ew_klo[21];
    unsigned char et_combo[124], et_k[124], et_dst[124];
    unsigned char h_xy[36], h_l3[36];
    short cgoff[3][3][5];
    unsigned char om_xy[196], om_l1[196], om_l2[196], om_mn[196];
    short ds_t[196], ds_off[196];
    unsigned char ds_ew[196], ds_len[196];
    int n_et, n_combo, m_total;
};

constexpr int trif(int x, int y) {
    int lo = x < y ? x : y, hi = x < y ? y : x;
    return hi * (hi + 1) / 2 + lo;
}

constexpr int shellof(int x) { return x < 3 ? 0 : (x < 5 ? 1 : 2); }

constexpr Tables makeTables() {
    Tables t{};
    for (int x = 0; x < 6; x++)
        for (int y = x; y < 6; y++) {
            t.tri_x[trif(x,y)] = (unsigned char)x;
            t.tri_y[trif(x,y)] = (unsigned char)y;
        }
    {
        int run = 0;
        for (int xy = 0; xy < 21; xy++) {
            int l2 = shellof(t.tri_x[xy]);
            int l1 = shellof(t.tri_y[xy]);
            if (l2 > l1) { int tmp = l1; l1 = l2; l2 = tmp; }
            int klo = (l1 - l2) * (l1 - l2);
            int khi = (l1 + l2 + 1) * (l1 + l2 + 1);
            t.ew_klo[xy] = (unsigned char)klo;
            t.ew_off[xy] = (unsigned char)run;
            run += khi - klo;
        }
    }
    const int base[3] = {0, 3, 5};
    const int adim[3] = {3, 2, 1};
    {
        int off = 0;
        for (int l1 = 0; l1 < 3; l1++)
            for (int l2 = 0; l2 <= l1; l2++)
                for (int l3 = l1 - l2; l3 <= l1 + l2; l3++) {
                    t.cgoff[l1][l2][l3] = (short)off;
                    off += (2*l1+1) * (2*l2+1) * (2*l3+1);
                }
    }
    {
        bool seenE[21][25] = {};
        short comboId[21][5] = {};
        for (int a = 0; a < 21; a++)
            for (int b = 0; b < 5; b++) comboId[a][b] = -1;
        int ne = 0, nc = 0;
        for (int l1 = 0; l1 < 3; l1++)
            for (int l2 = 0; l2 <= l1; l2++)
                for (int xa = 0; xa < adim[l1]; xa++)
                    for (int xb = 0; xb < adim[l2]; xb++) {
                        int xy = trif(base[l1] + xa, base[l2] + xb);
                        for (int l3 = l1 - l2; l3 <= l1 + l2; l3++) {
                            if (comboId[xy][l3] < 0) {
                                comboId[xy][l3] = (short)nc;
                                t.h_xy[nc] = (unsigned char)xy;
                                t.h_l3[nc] = (unsigned char)l3;
                                nc++;
                            }
                            for (int ap = 0; ap < 2*l3 + 1; ap++) {
                                int k = l3*l3 + ap;
                                if (!seenE[xy][k]) {
                                    seenE[xy][k] = true;
                                    t.et_combo[ne] = (unsigned char)comboId[xy][l3];
                                    t.et_k[ne]  = (unsigned char)k;
                                    t.et_dst[ne] = (unsigned char)(t.ew_off[xy] + k - t.ew_klo[xy]);
                                    ne++;
                                }
                            }
                        }
                    }
        t.n_et = ne;
        t.n_combo = nc;
    }
    for (int r = 0; r < 14; r++)
        for (int c = 0; c < 14; c++) {
            int lr = r < 3 ? 0 : (r < 9 ? 1 : 2);
            int xr = r - (lr == 0 ? 0 : (lr == 1 ? 3 : 9));
            int lc = c < 3 ? 0 : (c < 9 ? 1 : 2);
            int xc = c - (lc == 0 ? 0 : (lc == 1 ? 3 : 9));
            int l1 = 0, l2 = 0, X = 0, Y = 0;
            if (lr >= lc) { l1 = lr; l2 = lc; X = xr; Y = xc; }
            else          { l1 = lc; l2 = lr; X = xc; Y = xr; }
            int N = 2*l2 + 1, A = adim[l1], B = adim[l2];
            int flat = X * (N * B) + Y;
            int b = flat % B; int tmp = flat / B;
            int a = tmp % A; tmp /= A;
            int n2 = tmp % N; int m = tmp / N;
            int idx = r * 14 + c;
            t.om_xy[idx] = (unsigned char)trif(base[l1] + a, base[l2] + b);
            t.om_l1[idx] = (unsigned char)l1;
            t.om_l2[idx] = (unsigned char)l2;
            t.om_mn[idx] = (unsigned char)(m * N + n2);
        }
    {
        const int lens[6] = {25, 15, 9, 5, 3, 1};
        int n = 0;
        int moff = 0;
        for (int li = 0; li < 6; li++)
            for (int tt = 0; tt < 196; tt++) {
                int l1 = t.om_l1[tt], l2 = t.om_l2[tt];
                int klo = (l1 - l2) * (l1 - l2);
                int khi = (l1 + l2 + 1) * (l1 + l2 + 1);
                if (khi - klo == lens[li]) {
                    t.ds_t[n] = (short)tt;
                    t.ds_ew[n] = t.ew_off[t.om_xy[tt]];
                    t.ds_len[n] = (unsigned char)(khi - klo);
                    t.ds_off[n] = (short)moff;
                    moff += khi - klo;
                    n++;
                }
            }
        t.m_total = moff;
    }
    return t;
}

__constant__ Tables TBc = makeTables();

// Global scratch (zero-initialized at module load; scan re-zeroes cntg)
__device__ float Hg[100 * 35 * 16];
__device__ float Mg[MMAX];
__device__ int cntg[100];
__device__ int fillg[100];
__device__ int permg[PERMCAP];
__device__ unsigned char tpg[PCAP];

// ============================================================================
// Setup kernel (grid=100, block=576):
//  - H[tp] for block tp; init permg; block0 builds Mg
//  - computes tpg[p] AND the per-type-pair histogram (smem agg -> cntg)
//    (cntg is zero at first launch; scan_kernel re-zeroes it for replays)
// ============================================================================
__global__ void h_kernel(const float* __restrict__ weight,
                         const float* __restrict__ s_col,
                         const float* __restrict__ p_col,
                         const float* __restrict__ d_col,
                         const int* __restrict__ Z,
                         const int* __restrict__ pairs,
                         const int* __restrict__ aidx, int Pn,
                         const __grid_constant__ CGParam cgp)
{
    __shared__ float coll[96];
    __shared__ int loc[100];
    int tid = threadIdx.x;
    if (tid < 96) {
        float v;
        if (tid < 48)      v = s_col[tid];
        else if (tid < 80) v = p_col[tid - 48];
        else               v = d_col[tid - 80];
        coll[tid] = v;
    }
    if (tid < 100) loc[tid] = 0;
    __syncthreads();
    {
        int gtid = blockIdx.x * 576 + tid;
        if (gtid < Pn) {
            int ai = aidx[gtid];
            int t1 = Z[pairs[2 * ai]];
            int t2 = Z[pairs[2 * ai + 1]];
            int tp = t1 * NT + t2;
            tpg[gtid] = (unsigned char)tp;
            atomicAdd(&loc[tp], 1);
        }
        for (int idx = gtid; idx < PERMCAP; idx += 100 * 576)
            permg[idx] = -1;
    }
    if (blockIdx.x == 0 && tid < 196) {
        int e = tid;
        int t  = TBc.ds_t[e];
        int l1 = TBc.om_l1[t], l2 = TBc.om_l2[t], mn = TBc.om_mn[t];
        int klo = (l1 - l2) * (l1 - l2);
        int len = TBc.ds_len[e], off = TBc.ds_off[e];
        for (int q = 0; q < len; q++) {
            int k = klo + q;
            int l3 = (k < 1) ? 0 : (k < 4) ? 1 : (k < 9) ? 2 : (k < 16) ? 3 : 4;
            int ap = k - l3 * l3;
            Mg[off + q] = cgp.v[TBc.cgoff[l1][l2][l3] + mn * (2 * l3 + 1) + ap];
        }
    }
    __syncthreads();
    if (tid < 100 && loc[tid] > 0) atomicAdd(&cntg[tid], loc[tid]);
    if (tid >= 560) return;
    int tp = blockIdx.x;
    int t1 = tp / NT, t2 = tp % NT;
    int combo = tid >> 4, c = tid & 15;
    int xy = TBc.h_xy[combo], l3 = TBc.h_l3[combo];
    int x = TBc.tri_x[xy], y = TBc.tri_y[xy];
    const float* w1 = weight + (size_t)(t1 * NT + t2) * 1280 + l3 * 256;
    const float* w2 = weight + (size_t)(t2 * NT + t1) * 1280 + l3 * 256;
    float acc = 0.f;
    #pragma unroll
    for (int b = 0; b < 16; b++)
        acc += coll[x * 16 + b] * coll[y * 16 + b] * (w1[b * 16 + c] + w2[b * 16 + c]);
    Hg[(tp * 35 + combo) * 16 + c] = acc;
}

// ============================================================================
// Scan (reads cntg, writes fillg, re-zeroes cntg for graph replay)
// ============================================================================
__global__ void scan_kernel() {
    __shared__ int c_s[100];
    int tid = threadIdx.x;
    if (tid < 100) {
        c_s[tid] = cntg[tid];
        cntg[tid] = 0;
    }
    __syncthreads();
    if (tid == 0) {
        int run = 0;
        for (int b = 0; b < 100; b++) {
            int c = c_s[b];
            c_s[b] = run;
            run += (c + 7) & ~7;
        }
    }
    __syncthreads();
    if (tid < 100) fillg[tid] = c_s[tid];
}

__global__ void scatter_kernel(int Pn) {
    __shared__ int loc[100];
    __shared__ int base_s[100];
    int tid = threadIdx.x;
    if (tid < 100) loc[tid] = 0;
    __syncthreads();
    int p = blockIdx.x * blockDim.x + tid;
    int tp = -1, rank = 0;
    if (p < Pn) {
        tp = (int)tpg[p];
        rank = atomicAdd(&loc[tp], 1);
    }
    __syncthreads();
    if (tid < 100)
        base_s[tid] = (loc[tid] > 0) ? atomicAdd(&fillg[tid], loc[tid]) : 0;
    __syncthreads();
    if (p < Pn)
        permg[base_s[tp] + rank] = p;
}

// ============================================================================
// Main kernel: one warp per pair, 8 pairs/CTA, CTA-uniform type-pair.
// Dyn smem/warp (floats): Ewp[0,124) (rbf overlays [0,32))
//                         gsh[124,204)  cinS[204,629) (25 rows stride 17)
// ============================================================================
#define WSLOT 632

__global__ void __launch_bounds__(256, 6) op_kernel(
    const float* __restrict__ c0, const float* __restrict__ c1,
    const float* __restrict__ c2, const float* __restrict__ c3,
    const float* __restrict__ c4,
    const float* __restrict__ Rpos, const float* __restrict__ w_rad,
    const int* __restrict__ pairs,
    float* __restrict__ out)
{
    __shared__ __align__(16) float Hs[35 * 17 + 5];
    __shared__ __align__(16) float Mv[MMAX];
    __shared__ unsigned char etc_s[121], etk_s[121], etd_s[121];
    __shared__ short dst_s[196], dsoff_s[196];
    __shared__ unsigned char dsew_s[196], dslen_s[196];
    __shared__ int ctaTp;
    extern __shared__ __align__(16) float dyn[];

    int tid = threadIdx.x, w = tid >> 5, lane = tid & 31;
    int base = blockIdx.x * WARPS;

    if (tid == 0) {
        int pe0 = permg[base];
        ctaTp = (pe0 >= 0) ? (int)tpg[pe0] : -1;
    }
    for (int idx = tid; idx < TBc.m_total; idx += 256) Mv[idx] = Mg[idx];
    if (tid < 121) {
        etc_s[tid] = TBc.et_combo[tid];
        etk_s[tid] = TBc.et_k[tid];
        etd_s[tid] = TBc.et_dst[tid];
    }
    if (tid < 196) {
        dst_s[tid]   = TBc.ds_t[tid];
        dsoff_s[tid] = TBc.ds_off[tid];
        dsew_s[tid]  = TBc.ds_ew[tid];
        dslen_s[tid] = TBc.ds_len[tid];
    }
    __syncthreads();
    int tpc = ctaTp;
    if (tpc < 0) return;
    {
        const float* Hsrc = Hg + (size_t)tpc * 560;
        for (int idx = tid; idx < 560; idx += 256) {
            int combo = idx >> 4, c = idx & 15;
            Hs[combo * 17 + c] = Hsrc[idx];
        }
    }
    __syncthreads();

    int pe = permg[base + w];
    if (pe < 0) return;

    float* Wp   = dyn + w * WSLOT;
    float* Ewp  = Wp;
    float* rbf  = Wp;
    float* gsh  = Wp + 124;
    float* cinS = Wp + 204;

    int i = pairs[2 * pe], j = pairs[2 * pe + 1];

    float dx = Rpos[3*i+0] - Rpos[3*j+0];
    float dy = Rpos[3*i+1] - Rpos[3*j+1];
    float dz = Rpos[3*i+2] - Rpos[3*j+2];
    float d  = sqrtf(dx*dx + dy*dy + dz*dz);
    float env = (d < RCUTF) ? 0.5f * (cosf(PI_F * d / RCUTF) + 1.0f) : 0.0f;
    rbf[lane] = sinf((float)(lane + 1) * PI_F * d / RCUTF) * env;
    __syncwarp();

    int f = lane & 15, h = lane >> 4;

    // ---- Phase A: g[l][f] = sum_k rbf[k]*w_rad[l][k][f]
    //  (rbf via 8 LDS.128, reused across this lane's 2-3 outputs) ----
    {
        const float4* rv = (const float4*)rbf;
        int lbase = h ? 3 : 0;
        int nl = h ? 2 : 3;
        float a0 = 0.f, a1 = 0.f, a2 = 0.f;
        const float* wb = w_rad + lbase * 512 + f;
        #pragma unroll
        for (int q = 0; q < 8; q++) {
            float4 r4 = rv[q];
            const float* wl0 = wb + q * 64;
            a0 = fmaf(r4.x, __ldg(wl0 +  0), a0);
            a0 = fmaf(r4.y, __ldg(wl0 + 16), a0);
            a0 = fmaf(r4.z, __ldg(wl0 + 32), a0);
            a0 = fmaf(r4.w, __ldg(wl0 + 48), a0);
            const float* wl1 = wl0 + 512;
            a1 = fmaf(r4.x, __ldg(wl1 +  0), a1);
            a1 = fmaf(r4.y, __ldg(wl1 + 16), a1);
            a1 = fmaf(r4.z, __ldg(wl1 + 32), a1);
            a1 = fmaf(r4.w, __ldg(wl1 + 48), a1);
            if (nl > 2) {
                const float* wl2 = wl1 + 512;
                a2 = fmaf(r4.x, __ldg(wl2 +  0), a2);
                a2 = fmaf(r4.y, __ldg(wl2 + 16), a2);
                a2 = fmaf(r4.z, __ldg(wl2 + 32), a2);
                a2 = fmaf(r4.w, __ldg(wl2 + 48), a2);
            }
        }
        __syncwarp();   // rbf reads done before Ewp overlay writes later
        gsh[(lbase + 0) * 16 + f] = a0;
        gsh[(lbase + 1) * 16 + f] = a1;
        if (nl > 2) gsh[(lbase + 2) * 16 + f] = a2;
    }
    __syncwarp();

    // ---- Stage cin[k=l^2+m][c] = g[l][c]*(ci+cj), stride 17 ----
    {
        const float* clp[5] = {c0, c1, c2, c3, c4};
        #pragma unroll
        for (int l = 0; l < 5; l++) {
            const int nm = 2 * l + 1;
            const float* ci = clp[l] + (size_t)i * 16 * nm;
            const float* cj = clp[l] + (size_t)j * 16 * nm;
            for (int idx = lane; idx < 16 * nm; idx += 32) {
                int c = idx / nm, m = idx - c * nm;
                cinS[(l * l + m) * 17 + c] = gsh[l * 16 + c] * (ci[idx] + cj[idx]);
            }
        }
    }
    __syncwarp();

    // ---- Phase C': packed E[dst] = sum_c Hs[combo][c] * cin[k][c] ----
    for (int e = lane; e < 121; e += 32) {
        int combo = etc_s[e], k = etk_s[e], dst = etd_s[e];
        const float* Hr = Hs + combo * 17;
        const float* cr = cinS + k * 17;
        float acc = 0.f;
        #pragma unroll
        for (int c = 0; c < 16; c++)
            acc = fmaf(Hr[c], cr[c], acc);
        Ewp[dst] = acc;
    }
    __syncwarp();

    // ---- Phase D: out[t] = sum_q Mv[off+q] * Ewp[ew+q] ----
    float* op = out + (size_t)pe * 196;
    for (int e = lane; e < 196; e += 32) {
        int t = dst_s[e];
        const float* Mr = Mv + dsoff_s[e];
        const float* Er = Ewp + dsew_s[e];
        int len = dslen_s[e];
        float acc = 0.f;
        for (int q = 0; q < len; q++)
            acc = fmaf(Mr[q], Er[q], acc);
        op[t] = acc;
    }
}

// ============================================================================
// Launch
// ============================================================================
extern "C" void kernel_launch(void* const* d_in, const int* in_sizes, int n_in,
                              void* d_out, int out_size) {
    const float* c0    = (const float*)d_in[0];
    const float* c1    = (const float*)d_in[1];
    const float* c2    = (const float*)d_in[2];
    const float* c3    = (const float*)d_in[3];
    const float* c4    = (const float*)d_in[4];
    const float* Rpos  = (const float*)d_in[5];
    const float* w_rad = (const float*)d_in[6];
    const float* wgt   = (const float*)d_in[7];
    const float* s_col = (const float*)d_in[8];
    const float* p_col = (const float*)d_in[9];
    const float* d_col = (const float*)d_in[10];
    const int*   Z     = (const int*)d_in[11];
    const int*   pairs = (const int*)d_in[12];
    const int*   aidx  = (const int*)d_in[13];
    float* out = (float*)d_out;

    int Pn = in_sizes[13];

    CGParam cg;
    fill_cg(cg.v);

    h_kernel<<<100, 576>>>(wgt, s_col, p_col, d_col, Z, pairs, aidx, Pn, cg);
    scan_kernel<<<1, 128>>>();
    scatter_kernel<<<(Pn + 255) / 256, 256>>>(Pn);

    size_t shmem = (size_t)WARPS * WSLOT * sizeof(float);
    cudaFuncSetAttribute(op_kernel, cudaFuncAttributeMaxDynamicSharedMemorySize, (int)shmem);
    int gridMain = (Pn + 700 + 7) / 8;
    op_kernel<<<gridMain, 256, shmem>>>(c0, c1, c2, c3, c4, Rpos, w_rad,
                                        pairs, out);
}

// round 13
// speedup vs baseline: 1.7128x; 1.2970x over previous
#include <cuda_runtime.h>
#include <math.h>
#include <stdint.h>
#include <string.h>

#define PI_F 3.14159265358979323846f
#define RCUTF 5.0f
#define NT 10
#define WARPS 8
#define PPC 16
#define PERMCAP 51712
#define PCAP 50048
#define MMAX 2176

// ============================================================================
// Host-side exact replication of numpy RandomState(seed).standard_normal(...)
// ============================================================================
struct MT19937 {
    uint32_t mt[624];
    int mti;
    void seed(uint32_t s) {
        mt[0] = s;
        for (int i = 1; i < 624; i++)
            mt[i] = 1812433253u * (mt[i-1] ^ (mt[i-1] >> 30)) + (uint32_t)i;
        mti = 624;
    }
    uint32_t next() {
        if (mti >= 624) {
            for (int i = 0; i < 624; i++) {
                uint32_t y = (mt[i] & 0x80000000u) | (mt[(i+1) % 624] & 0x7fffffffu);
                mt[i] = mt[(i+397) % 624] ^ (y >> 1) ^ ((y & 1u) ? 2567483615u : 0u);
            }
            mti = 0;
        }
        uint32_t y = mt[mti++];
        y ^= y >> 11;
        y ^= (y << 7)  & 2636928640u;
        y ^= (y << 15) & 4022730752u;
        y ^= y >> 18;
        return y;
    }
    double rdouble() {
        uint32_t a = next() >> 5, b = next() >> 6;
        return (a * 67108864.0 + b) / 9007199254740992.0;
    }
};
struct GaussGen {
    MT19937 mt;
    bool has;
    double cached;
    void init(uint32_t s) { mt.seed(s); has = false; cached = 0.0; }
    double next() {
        if (has) { has = false; return cached; }
        double x1, x2, r2;
        do {
            x1 = 2.0 * mt.rdouble() - 1.0;
            x2 = 2.0 * mt.rdouble() - 1.0;
            r2 = x1 * x1 + x2 * x2;
        } while (r2 >= 1.0 || r2 == 0.0);
        double f = sqrt(-2.0 * log(r2) / r2);
        cached = f * x1; has = true;
        return f * x2;
    }
};

struct CGParam { float v[966]; };

static void fill_cg(float* out) {
    int off = 0;
    for (int l1 = 0; l1 < 3; l1++)
        for (int l2 = 0; l2 <= l1; l2++)
            for (int l3 = l1 - l2; l3 <= l1 + l2; l3++) {
                GaussGen g; g.init((uint32_t)(1000 + l1*100 + l2*10 + l3));
                int cnt = (2*l1+1) * (2*l2+1) * (2*l3+1);
                for (int q = 0; q < cnt; q++)
                    out[off++] = (float)g.next();
            }
}

// ============================================================================
// Compile-time index tables
// ============================================================================
struct Tables {
    unsigned char tri_x[21], tri_y[21];
    unsigned char ew_off[21], ew_klo[21];
    unsigned char et_combo[124], et_k[124], et_dst[124];
    unsigned char h_xy[36], h_l3[36];
    short cgoff[3][3][5];
    unsigned char om_xy[196], om_l1[196], om_l2[196], om_mn[196];
    short ds_t[196], ds_off[196];
    unsigned char ds_ew[196], ds_len[196];
    int n_et, n_combo, m_total;
};

constexpr int trif(int x, int y) {
    int lo = x < y ? x : y, hi = x < y ? y : x;
    return hi * (hi + 1) / 2 + lo;
}

constexpr int shellof(int x) { return x < 3 ? 0 : (x < 5 ? 1 : 2); }

constexpr Tables makeTables() {
    Tables t{};
    for (int x = 0; x < 6; x++)
        for (int y = x; y < 6; y++) {
            t.tri_x[trif(x,y)] = (unsigned char)x;
            t.tri_y[trif(x,y)] = (unsigned char)y;
        }
    {
        int run = 0;
        for (int xy = 0; xy < 21; xy++) {
            int l2 = shellof(t.tri_x[xy]);
            int l1 = shellof(t.tri_y[xy]);
            if (l2 > l1) { int tmp = l1; l1 = l2; l2 = tmp; }
            int klo = (l1 - l2) * (l1 - l2);
            int khi = (l1 + l2 + 1) * (l1 + l2 + 1);
            t.ew_klo[xy] = (unsigned char)klo;
            t.ew_off[xy] = (unsigned char)run;
            run += khi - klo;
        }
    }
    const int base[3] = {0, 3, 5};
    const int adim[3] = {3, 2, 1};
    {
        int off = 0;
        for (int l1 = 0; l1 < 3; l1++)
            for (int l2 = 0; l2 <= l1; l2++)
                for (int l3 = l1 - l2; l3 <= l1 + l2; l3++) {
                    t.cgoff[l1][l2][l3] = (short)off;
                    off += (2*l1+1) * (2*l2+1) * (2*l3+1);
                }
    }
    {
        bool seenE[21][25] = {};
        short comboId[21][5] = {};
        for (int a = 0; a < 21; a++)
            for (int b = 0; b < 5; b++) comboId[a][b] = -1;
        int ne = 0, nc = 0;
        for (int l1 = 0; l1 < 3; l1++)
            for (int l2 = 0; l2 <= l1; l2++)
                for (int xa = 0; xa < adim[l1]; xa++)
                    for (int xb = 0; xb < adim[l2]; xb++) {
                        int xy = trif(base[l1] + xa, base[l2] + xb);
                        for (int l3 = l1 - l2; l3 <= l1 + l2; l3++) {
                            if (comboId[xy][l3] < 0) {
                                comboId[xy][l3] = (short)nc;
                                t.h_xy[nc] = (unsigned char)xy;
                                t.h_l3[nc] = (unsigned char)l3;
                                nc++;
                            }
                            for (int ap = 0; ap < 2*l3 + 1; ap++) {
                                int k = l3*l3 + ap;
                                if (!seenE[xy][k]) {
                                    seenE[xy][k] = true;
                                    t.et_combo[ne] = (unsigned char)comboId[xy][l3];
                                    t.et_k[ne]  = (unsigned char)k;
                                    t.et_dst[ne] = (unsigned char)(t.ew_off[xy] + k - t.ew_klo[xy]);
                                    ne++;
                                }
                            }
                        }
                    }
        t.n_et = ne;
        t.n_combo = nc;
    }
    for (int r = 0; r < 14; r++)
        for (int c = 0; c < 14; c++) {
            int lr = r < 3 ? 0 : (r < 9 ? 1 : 2);
            int xr = r - (lr == 0 ? 0 : (lr == 1 ? 3 : 9));
            int lc = c < 3 ? 0 : (c < 9 ? 1 : 2);
            int xc = c - (lc == 0 ? 0 : (lc == 1 ? 3 : 9));
            int l1 = 0, l2 = 0, X = 0, Y = 0;
            if (lr >= lc) { l1 = lr; l2 = lc; X = xr; Y = xc; }
            else          { l1 = lc; l2 = lr; X = xc; Y = xr; }
            int N = 2*l2 + 1, A = adim[l1], B = adim[l2];
            int flat = X * (N * B) + Y;
            int b = flat % B; int tmp = flat / B;
            int a = tmp % A; tmp /= A;
            int n2 = tmp % N; int m = tmp / N;
            int idx = r * 14 + c;
            t.om_xy[idx] = (unsigned char)trif(base[l1] + a, base[l2] + b);
            t.om_l1[idx] = (unsigned char)l1;
            t.om_l2[idx] = (unsigned char)l2;
            t.om_mn[idx] = (unsigned char)(m * N + n2);
        }
    {
        const int lens[6] = {25, 15, 9, 5, 3, 1};
        int n = 0;
        int moff = 0;
        for (int li = 0; li < 6; li++)
            for (int tt = 0; tt < 196; tt++) {
                int l1 = t.om_l1[tt], l2 = t.om_l2[tt];
                int klo = (l1 - l2) * (l1 - l2);
                int khi = (l1 + l2 + 1) * (l1 + l2 + 1);
                if (khi - klo == lens[li]) {
                    t.ds_t[n] = (short)tt;
                    t.ds_ew[n] = t.ew_off[t.om_xy[tt]];
                    t.ds_len[n] = (unsigned char)(khi - klo);
                    t.ds_off[n] = (short)moff;
                    moff += khi - klo;
                    n++;
                }
            }
        t.m_total = moff;
    }
    return t;
}

__constant__ Tables TBc = makeTables();

// Global scratch (zero at module load; scan re-zeroes cntg for replays)
__device__ float Hg[100 * 35 * 16];
__device__ float Mg[MMAX];
__device__ int cntg[100];
__device__ int fillg[100];
__device__ int permg[PERMCAP];
__device__ unsigned char tpg[PCAP];

// ============================================================================
// Setup kernel (grid=100, block=576)
// ============================================================================
__global__ void h_kernel(const float* __restrict__ weight,
                         const float* __restrict__ s_col,
                         const float* __restrict__ p_col,
                         const float* __restrict__ d_col,
                         const int* __restrict__ Z,
                         const int* __restrict__ pairs,
                         const int* __restrict__ aidx, int Pn,
                         const __grid_constant__ CGParam cgp)
{
    __shared__ float coll[96];
    __shared__ int loc[100];
    int tid = threadIdx.x;
    if (tid < 96) {
        float v;
        if (tid < 48)      v = s_col[tid];
        else if (tid < 80) v = p_col[tid - 48];
        else               v = d_col[tid - 80];
        coll[tid] = v;
    }
    if (tid < 100) loc[tid] = 0;
    __syncthreads();
    {
        int gtid = blockIdx.x * 576 + tid;
        if (gtid < Pn) {
            int ai = aidx[gtid];
            int t1 = Z[pairs[2 * ai]];
            int t2 = Z[pairs[2 * ai + 1]];
            int tp = t1 * NT + t2;
            tpg[gtid] = (unsigned char)tp;
            atomicAdd(&loc[tp], 1);
        }
        for (int idx = gtid; idx < PERMCAP; idx += 100 * 576)
            permg[idx] = -1;
    }
    if (blockIdx.x == 0 && tid < 196) {
        int e = tid;
        int t  = TBc.ds_t[e];
        int l1 = TBc.om_l1[t], l2 = TBc.om_l2[t], mn = TBc.om_mn[t];
        int klo = (l1 - l2) * (l1 - l2);
        int len = TBc.ds_len[e], off = TBc.ds_off[e];
        for (int q = 0; q < len; q++) {
            int k = klo + q;
            int l3 = (k < 1) ? 0 : (k < 4) ? 1 : (k < 9) ? 2 : (k < 16) ? 3 : 4;
            int ap = k - l3 * l3;
            Mg[off + q] = cgp.v[TBc.cgoff[l1][l2][l3] + mn * (2 * l3 + 1) + ap];
        }
    }
    __syncthreads();
    if (tid < 100 && loc[tid] > 0) atomicAdd(&cntg[tid], loc[tid]);
    if (tid >= 560) return;
    int tp = blockIdx.x;
    int t1 = tp / NT, t2 = tp % NT;
    int combo = tid >> 4, c = tid & 15;
    int xy = TBc.h_xy[combo], l3 = TBc.h_l3[combo];
    int x = TBc.tri_x[xy], y = TBc.tri_y[xy];
    const float* w1 = weight + (size_t)(t1 * NT + t2) * 1280 + l3 * 256;
    const float* w2 = weight + (size_t)(t2 * NT + t1) * 1280 + l3 * 256;
    float acc = 0.f;
    #pragma unroll
    for (int b = 0; b < 16; b++)
        acc += coll[x * 16 + b] * coll[y * 16 + b] * (w1[b * 16 + c] + w2[b * 16 + c]);
    Hg[(tp * 35 + combo) * 16 + c] = acc;
}

// ============================================================================
// Scan (reads cntg, writes fillg, re-zeroes cntg; bins padded to PPC)
// ============================================================================
__global__ void scan_kernel() {
    __shared__ int c_s[100];
    int tid = threadIdx.x;
    if (tid < 100) {
        c_s[tid] = cntg[tid];
        cntg[tid] = 0;
    }
    __syncthreads();
    if (tid == 0) {
        int run = 0;
        for (int b = 0; b < 100; b++) {
            int c = c_s[b];
            c_s[b] = run;
            run += (c + PPC - 1) & ~(PPC - 1);
        }
    }
    __syncthreads();
    if (tid < 100) fillg[tid] = c_s[tid];
}

__global__ void scatter_kernel(int Pn) {
    __shared__ int loc[100];
    __shared__ int base_s[100];
    int tid = threadIdx.x;
    if (tid < 100) loc[tid] = 0;
    __syncthreads();
    int p = blockIdx.x * blockDim.x + tid;
    int tp = -1, rank = 0;
    if (p < Pn) {
        tp = (int)tpg[p];
        rank = atomicAdd(&loc[tp], 1);
    }
    __syncthreads();
    if (tid < 100)
        base_s[tid] = (loc[tid] > 0) ? atomicAdd(&fillg[tid], loc[tid]) : 0;
    __syncthreads();
    if (p < Pn)
        permg[base_s[tp] + rank] = p;
}

// ============================================================================
// Main kernel: 2 pairs per warp (INTERLEAVED), 16 pairs/CTA, uniform tp.
// Per-warp dyn smem (floats):
//   EwpA[0,124)  EwpB[124,248)   (rbfA/rbfB overlay first 32 of each)
//   gshA[248,328) gshB[328,408)
//   cinA[408,833) cinB[833,1258)   (25 rows, stride 17)
// WSLOT=1260 -> dyn 40.3KB; 4 CTAs/SM.
// ============================================================================
#define WSLOT 1260

__global__ void __launch_bounds__(256, 4) op_kernel(
    const float* __restrict__ c0, const float* __restrict__ c1,
    const float* __restrict__ c2, const float* __restrict__ c3,
    const float* __restrict__ c4,
    const float* __restrict__ Rpos, const float* __restrict__ w_rad,
    const int* __restrict__ pairs,
    float* __restrict__ out)
{
    __shared__ __align__(16) float Hs[35 * 17 + 5];
    __shared__ __align__(16) float Mv[MMAX];
    __shared__ unsigned int etp_s[121];   // combo<<16 | k<<8 | dst
    __shared__ unsigned int dsp_s[196];   // t<<24 | off<<12 | ew<<5 | len
    __shared__ int ctaTp;
    extern __shared__ __align__(16) float dyn[];

    int tid = threadIdx.x, w = tid >> 5, lane = tid & 31;
    int base = blockIdx.x * PPC;

    if (tid == 0) {
        int pe0 = permg[base];
        ctaTp = (pe0 >= 0) ? (int)tpg[pe0] : -1;
    }
    for (int idx = tid; idx < TBc.m_total; idx += 256) Mv[idx] = Mg[idx];
    if (tid < 121)
        etp_s[tid] = ((unsigned)TBc.et_combo[tid] << 16) |
                     ((unsigned)TBc.et_k[tid] << 8) |
                     (unsigned)TBc.et_dst[tid];
    if (tid < 196)
        dsp_s[tid] = ((unsigned)TBc.ds_t[tid] << 24) |
                     ((unsigned)TBc.ds_off[tid] << 12) |
                     ((unsigned)TBc.ds_ew[tid] << 5) |
                     (unsigned)TBc.ds_len[tid];
    __syncthreads();
    int tpc = ctaTp;
    if (tpc < 0) return;
    {
        const float* Hsrc = Hg + (size_t)tpc * 560;
        for (int idx = tid; idx < 560; idx += 256) {
            int combo = idx >> 4, c = idx & 15;
            Hs[combo * 17 + c] = Hsrc[idx];
        }
    }
    __syncthreads();

    int peA = permg[base + w];
    if (peA < 0) return;
    int peB = permg[base + 8 + w];
    if (peB < 0) peB = peA;   // duplicate work; same value written twice

    float* Wp   = dyn + w * WSLOT;
    float* EwpA = Wp;
    float* EwpB = Wp + 124;
    float* rbfA = EwpA;
    float* rbfB = EwpB;
    float* gshA = Wp + 248;
    float* gshB = Wp + 328;
    float* cinA = Wp + 408;
    float* cinB = Wp + 833;

    int iA = pairs[2 * peA], jA = pairs[2 * peA + 1];
    int iB = pairs[2 * peB], jB = pairs[2 * peB + 1];

    {
        float dxA = Rpos[3*iA+0] - Rpos[3*jA+0];
        float dyA = Rpos[3*iA+1] - Rpos[3*jA+1];
        float dzA = Rpos[3*iA+2] - Rpos[3*jA+2];
        float dA  = sqrtf(dxA*dxA + dyA*dyA + dzA*dzA);
        float envA = (dA < RCUTF) ? 0.5f * (cosf(PI_F * dA / RCUTF) + 1.0f) : 0.0f;
        rbfA[lane] = sinf((float)(lane + 1) * PI_F * dA / RCUTF) * envA;
        float dxB = Rpos[3*iB+0] - Rpos[3*jB+0];
        float dyB = Rpos[3*iB+1] - Rpos[3*jB+1];
        float dzB = Rpos[3*iB+2] - Rpos[3*jB+2];
        float dB  = sqrtf(dxB*dxB + dyB*dyB + dzB*dzB);
        float envB = (dB < RCUTF) ? 0.5f * (cosf(PI_F * dB / RCUTF) + 1.0f) : 0.0f;
        rbfB[lane] = sinf((float)(lane + 1) * PI_F * dB / RCUTF) * envB;
    }
    __syncwarp();

    int f = lane & 15, h = lane >> 4;

    // ---- Phase A (dual): one w_rad load feeds both pairs ----
    {
        const float4* rvA = (const float4*)rbfA;
        const float4* rvB = (const float4*)rbfB;
        int lbase = h ? 3 : 0;
        int nl = h ? 2 : 3;
        float a0A = 0.f, a1A = 0.f, a2A = 0.f;
        float a0B = 0.f, a1B = 0.f, a2B = 0.f;
        const float* wb = w_rad + lbase * 512 + f;
        #pragma unroll
        for (int q = 0; q < 8; q++) {
            float4 rA = rvA[q];
            float4 rB = rvB[q];
            const float* wl0 = wb + q * 64;
            float w00 = __ldg(wl0 +  0), w01 = __ldg(wl0 + 16);
            float w02 = __ldg(wl0 + 32), w03 = __ldg(wl0 + 48);
            a0A = fmaf(rA.x, w00, a0A); a0B = fmaf(rB.x, w00, a0B);
            a0A = fmaf(rA.y, w01, a0A); a0B = fmaf(rB.y, w01, a0B);
            a0A = fmaf(rA.z, w02, a0A); a0B = fmaf(rB.z, w02, a0B);
            a0A = fmaf(rA.w, w03, a0A); a0B = fmaf(rB.w, w03, a0B);
            const float* wl1 = wl0 + 512;
            float w10 = __ldg(wl1 +  0), w11 = __ldg(wl1 + 16);
            float w12 = __ldg(wl1 + 32), w13 = __ldg(wl1 + 48);
            a1A = fmaf(rA.x, w10, a1A); a1B = fmaf(rB.x, w10, a1B);
            a1A = fmaf(rA.y, w11, a1A); a1B = fmaf(rB.y, w11, a1B);
            a1A = fmaf(rA.z, w12, a1A); a1B = fmaf(rB.z, w12, a1B);
            a1A = fmaf(rA.w, w13, a1A); a1B = fmaf(rB.w, w13, a1B);
            if (nl > 2) {
                const float* wl2 = wl1 + 512;
                float w20 = __ldg(wl2 +  0), w21 = __ldg(wl2 + 16);
                float w22 = __ldg(wl2 + 32), w23 = __ldg(wl2 + 48);
                a2A = fmaf(rA.x, w20, a2A); a2B = fmaf(rB.x, w20, a2B);
                a2A = fmaf(rA.y, w21, a2A); a2B = fmaf(rB.y, w21, a2B);
                a2A = fmaf(rA.z, w22, a2A); a2B = fmaf(rB.z, w22, a2B);
                a2A = fmaf(rA.w, w23, a2A); a2B = fmaf(rB.w, w23, a2B);
            }
        }
        __syncwarp();
        gshA[(lbase + 0) * 16 + f] = a0A;
        gshB[(lbase + 0) * 16 + f] = a0B;
        gshA[(lbase + 1) * 16 + f] = a1A;
        gshB[(lbase + 1) * 16 + f] = a1B;
        if (nl > 2) {
            gshA[(lbase + 2) * 16 + f] = a2A;
            gshB[(lbase + 2) * 16 + f] = a2B;
        }
    }
    __syncwarp();

    // ---- Stage cin (dual streams) ----
    {
        const float* clp[5] = {c0, c1, c2, c3, c4};
        #pragma unroll
        for (int l = 0; l < 5; l++) {
            const int nm = 2 * l + 1;
            const float* ciA = clp[l] + (size_t)iA * 16 * nm;
            const float* cjA = clp[l] + (size_t)jA * 16 * nm;
            const float* ciB = clp[l] + (size_t)iB * 16 * nm;
            const float* cjB = clp[l] + (size_t)jB * 16 * nm;
            for (int idx = lane; idx < 16 * nm; idx += 32) {
                int c = idx / nm, m = idx - c * nm;
                int dst = (l * l + m) * 17 + c;
                cinA[dst] = gshA[l * 16 + c] * (ciA[idx] + cjA[idx]);
                cinB[dst] = gshB[l * 16 + c] * (ciB[idx] + cjB[idx]);
            }
        }
    }
    __syncwarp();

    // ---- Phase C' (dual): one H row feeds both pairs ----
    for (int e = lane; e < 121; e += 32) {
        unsigned pk = etp_s[e];
        int combo = pk >> 16, k = (pk >> 8) & 0xFF, dst = pk & 0xFF;
        const float* Hr = Hs + combo * 17;
        const float* crA = cinA + k * 17;
        const float* crB = cinB + k * 17;
        float accA = 0.f, accB = 0.f;
        #pragma unroll
        for (int c = 0; c < 16; c++) {
            float hv = Hr[c];
            accA = fmaf(hv, crA[c], accA);
            accB = fmaf(hv, crB[c], accB);
        }
        EwpA[dst] = accA;
        EwpB[dst] = accB;
    }
    __syncwarp();

    // ---- Phase D (dual): one M value feeds both pairs ----
    float* opA = out + (size_t)peA * 196;
    float* opB = out + (size_t)peB * 196;
    for (int e = lane; e < 196; e += 32) {
        unsigned pk = dsp_s[e];
        int t = pk >> 24, off = (pk >> 12) & 0xFFF, ew = (pk >> 5) & 0x7F, len = pk & 0x1F;
        const float* Mr = Mv + off;
        const float* ErA = EwpA + ew;
        const float* ErB = EwpB + ew;
        float accA = 0.f, accB = 0.f;
        for (int q = 0; q < len; q++) {
            float mv = Mr[q];
            accA = fmaf(mv, ErA[q], accA);
            accB = fmaf(mv, ErB[q], accB);
        }
        opA[t] = accA;
        opB[t] = accB;
    }
}

// ============================================================================
// Launch
// ============================================================================
extern "C" void kernel_launch(void* const* d_in, const int* in_sizes, int n_in,
                              void* d_out, int out_size) {
    const float* c0    = (const float*)d_in[0];
    const float* c1    = (const float*)d_in[1];
    const float* c2    = (const float*)d_in[2];
    const float* c3    = (const float*)d_in[3];
    const float* c4    = (const float*)d_in[4];
    const float* Rpos  = (const float*)d_in[5];
    const float* w_rad = (const float*)d_in[6];
    const float* wgt   = (const float*)d_in[7];
    const float* s_col = (const float*)d_in[8];
    const float* p_col = (const float*)d_in[9];
    const float* d_col = (const float*)d_in[10];
    const int*   Z     = (const int*)d_in[11];
    const int*   pairs = (const int*)d_in[12];
    const int*   aidx  = (const int*)d_in[13];
    float* out = (float*)d_out;

    int Pn = in_sizes[13];

    CGParam cg;
    fill_cg(cg.v);

    h_kernel<<<100, 576>>>(wgt, s_col, p_col, d_col, Z, pairs, aidx, Pn, cg);
    scan_kernel<<<1, 128>>>();
    scatter_kernel<<<(Pn + 255) / 256, 256>>>(Pn);

    size_t shmem = (size_t)WARPS * WSLOT * sizeof(float);
    cudaFuncSetAttribute(op_kernel, cudaFuncAttributeMaxDynamicSharedMemorySize, (int)shmem);
    int gridMain = (Pn + 100 * PPC + PPC - 1) / PPC;
    op_kernel<<<gridMain, 256, shmem>>>(c0, c1, c2, c3, c4, Rpos, w_rad,
                                        pairs, out);
}

// round 14
// speedup vs baseline: 1.7703x; 1.0336x over previous
#include <cuda_runtime.h>
#include <math.h>
#include <stdint.h>
#include <string.h>

#define PI_F 3.14159265358979323846f
#define RCUTF 5.0f
#define NT 10
#define WARPS 8
#define PPC 16
#define PERMCAP 51712
#define PCAP 50048
#define MMAX 1544
#define NDS 133

// ============================================================================
// Host-side exact replication of numpy RandomState(seed).standard_normal(...)
// ============================================================================
struct MT19937 {
    uint32_t mt[624];
    int mti;
    void seed(uint32_t s) {
        mt[0] = s;
        for (int i = 1; i < 624; i++)
            mt[i] = 1812433253u * (mt[i-1] ^ (mt[i-1] >> 30)) + (uint32_t)i;
        mti = 624;
    }
    uint32_t next() {
        if (mti >= 624) {
            for (int i = 0; i < 624; i++) {
                uint32_t y = (mt[i] & 0x80000000u) | (mt[(i+1) % 624] & 0x7fffffffu);
                mt[i] = mt[(i+397) % 624] ^ (y >> 1) ^ ((y & 1u) ? 2567483615u : 0u);
            }
            mti = 0;
        }
        uint32_t y = mt[mti++];
        y ^= y >> 11;
        y ^= (y << 7)  & 2636928640u;
        y ^= (y << 15) & 4022730752u;
        y ^= y >> 18;
        return y;
    }
    double rdouble() {
        uint32_t a = next() >> 5, b = next() >> 6;
        return (a * 67108864.0 + b) / 9007199254740992.0;
    }
};
struct GaussGen {
    MT19937 mt;
    bool has;
    double cached;
    void init(uint32_t s) { mt.seed(s); has = false; cached = 0.0; }
    double next() {
        if (has) { has = false; return cached; }
        double x1, x2, r2;
        do {
            x1 = 2.0 * mt.rdouble() - 1.0;
            x2 = 2.0 * mt.rdouble() - 1.0;
            r2 = x1 * x1 + x2 * x2;
        } while (r2 >= 1.0 || r2 == 0.0);
        double f = sqrt(-2.0 * log(r2) / r2);
        cached = f * x1; has = true;
        return f * x2;
    }
};

struct CGParam { float v[966]; };

static void fill_cg(float* out) {
    int off = 0;
    for (int l1 = 0; l1 < 3; l1++)
        for (int l2 = 0; l2 <= l1; l2++)
            for (int l3 = l1 - l2; l3 <= l1 + l2; l3++) {
                GaussGen g; g.init((uint32_t)(1000 + l1*100 + l2*10 + l3));
                int cnt = (2*l1+1) * (2*l2+1) * (2*l3+1);
                for (int q = 0; q < cnt; q++)
                    out[off++] = (float)g.next();
            }
}

// ============================================================================
// Compile-time index tables
// ============================================================================
struct Tables {
    unsigned char tri_x[21], tri_y[21];
    unsigned char ew_off[21], ew_klo[21];
    unsigned char et_combo[124], et_k[124], et_dst[124];
    unsigned char h_xy[36], h_l3[36];
    short cgoff[3][3][5];
    unsigned char om_xy[196], om_l1[196], om_l2[196], om_mn[196];
    // deduped output schedule (133 unique entries, desc len)
    short ds_t[NDS + 3], ds_t2[NDS + 3], ds_off[NDS + 3];
    unsigned char ds_ew[NDS + 3], ds_len[NDS + 3];
    int n_et, n_combo, m_total, n_ds;
};

constexpr int trif(int x, int y) {
    int lo = x < y ? x : y, hi = x < y ? y : x;
    return hi * (hi + 1) / 2 + lo;
}

constexpr int shellof(int x) { return x < 3 ? 0 : (x < 5 ? 1 : 2); }
constexpr int rshell(int r)  { return r < 3 ? 0 : (r < 9 ? 1 : 2); }

constexpr Tables makeTables() {
    Tables t{};
    for (int x = 0; x < 6; x++)
        for (int y = x; y < 6; y++) {
            t.tri_x[trif(x,y)] = (unsigned char)x;
            t.tri_y[trif(x,y)] = (unsigned char)y;
        }
    {
        int run = 0;
        for (int xy = 0; xy < 21; xy++) {
            int l2 = shellof(t.tri_x[xy]);
            int l1 = shellof(t.tri_y[xy]);
            if (l2 > l1) { int tmp = l1; l1 = l2; l2 = tmp; }
            int klo = (l1 - l2) * (l1 - l2);
            int khi = (l1 + l2 + 1) * (l1 + l2 + 1);
            t.ew_klo[xy] = (unsigned char)klo;
            t.ew_off[xy] = (unsigned char)run;
            run += khi - klo;
        }
    }
    const int base[3] = {0, 3, 5};
    const int adim[3] = {3, 2, 1};
    {
        int off = 0;
        for (int l1 = 0; l1 < 3; l1++)
            for (int l2 = 0; l2 <= l1; l2++)
                for (int l3 = l1 - l2; l3 <= l1 + l2; l3++) {
                    t.cgoff[l1][l2][l3] = (short)off;
                    off += (2*l1+1) * (2*l2+1) * (2*l3+1);
                }
    }
    {
        bool seenE[21][25] = {};
        short comboId[21][5] = {};
        for (int a = 0; a < 21; a++)
            for (int b = 0; b < 5; b++) comboId[a][b] = -1;
        int ne = 0, nc = 0;
        for (int l1 = 0; l1 < 3; l1++)
            for (int l2 = 0; l2 <= l1; l2++)
                for (int xa = 0; xa < adim[l1]; xa++)
                    for (int xb = 0; xb < adim[l2]; xb++) {
                        int xy = trif(base[l1] + xa, base[l2] + xb);
                        for (int l3 = l1 - l2; l3 <= l1 + l2; l3++) {
                            if (comboId[xy][l3] < 0) {
                                comboId[xy][l3] = (short)nc;
                                t.h_xy[nc] = (unsigned char)xy;
                                t.h_l3[nc] = (unsigned char)l3;
                                nc++;
                            }
                            for (int ap = 0; ap < 2*l3 + 1; ap++) {
                                int k = l3*l3 + ap;
                                if (!seenE[xy][k]) {
                                    seenE[xy][k] = true;
                                    t.et_combo[ne] = (unsigned char)comboId[xy][l3];
                                    t.et_k[ne]  = (unsigned char)k;
                                    t.et_dst[ne] = (unsigned char)(t.ew_off[xy] + k - t.ew_klo[xy]);
                                    ne++;
                                }
                            }
                        }
                    }
        t.n_et = ne;
        t.n_combo = nc;
    }
    for (int r = 0; r < 14; r++)
        for (int c = 0; c < 14; c++) {
            int lr = rshell(r);
            int xr = r - (lr == 0 ? 0 : (lr == 1 ? 3 : 9));
            int lc = rshell(c);
            int xc = c - (lc == 0 ? 0 : (lc == 1 ? 3 : 9));
            int l1 = 0, l2 = 0, X = 0, Y = 0;
            if (lr >= lc) { l1 = lr; l2 = lc; X = xr; Y = xc; }
            else          { l1 = lc; l2 = lr; X = xc; Y = xr; }
            int N = 2*l2 + 1, A = adim[l1], B = adim[l2];
            int flat = X * (N * B) + Y;
            int b = flat % B; int tmp = flat / B;
            int a = tmp % A; tmp /= A;
            int n2 = tmp % N; int m = tmp / N;
            int idx = r * 14 + c;
            t.om_xy[idx] = (unsigned char)trif(base[l1] + a, base[l2] + b);
            t.om_l1[idx] = (unsigned char)l1;
            t.om_l2[idx] = (unsigned char)l2;
            t.om_mn[idx] = (unsigned char)(m * N + n2);
        }
    // Deduped output schedule: skip cross-shell mirrors (keep r > c), desc len
    {
        const int lens[6] = {25, 15, 9, 5, 3, 1};
        int n = 0;
        int moff = 0;
        for (int li = 0; li < 6; li++)
            for (int tt = 0; tt < 196; tt++) {
                int r = tt / 14, c = tt % 14;
                int lr = rshell(r), lc = rshell(c);
                bool cross = (lr != lc);
                if (cross && r < c) continue;     // mirror dup — skip
                int l1 = t.om_l1[tt], l2 = t.om_l2[tt];
                int klo = (l1 - l2) * (l1 - l2);
                int khi = (l1 + l2 + 1) * (l1 + l2 + 1);
                if (khi - klo == lens[li]) {
                    t.ds_t[n] = (short)tt;
                    t.ds_t2[n] = (short)(cross ? (c * 14 + r) : tt);
                    t.ds_ew[n] = t.ew_off[t.om_xy[tt]];
                    t.ds_len[n] = (unsigned char)(khi - klo);
                    t.ds_off[n] = (short)moff;
                    moff += khi - klo;
                    n++;
                }
            }
        t.n_ds = n;       // 133
        t.m_total = moff; // 1537
    }
    return t;
}

__constant__ Tables TBc = makeTables();

// Global scratch (zero at module load; scan re-zeroes cntg for replays)
__device__ float Hg[100 * 35 * 16];
__device__ float Mg[MMAX];
__device__ int cntg[100];
__device__ int fillg[100];
__device__ int permg[PERMCAP];
__device__ unsigned char tpg[PCAP];

// ============================================================================
// Setup kernel (grid=100, block=576)
// ============================================================================
__global__ void h_kernel(const float* __restrict__ weight,
                         const float* __restrict__ s_col,
                         const float* __restrict__ p_col,
                         const float* __restrict__ d_col,
                         const int* __restrict__ Z,
                         const int* __restrict__ pairs,
                         const int* __restrict__ aidx, int Pn,
                         const __grid_constant__ CGParam cgp)
{
    __shared__ float coll[96];
    __shared__ int loc[100];
    int tid = threadIdx.x;
    if (tid < 96) {
        float v;
        if (tid < 48)      v = s_col[tid];
        else if (tid < 80) v = p_col[tid - 48];
        else               v = d_col[tid - 80];
        coll[tid] = v;
    }
    if (tid < 100) loc[tid] = 0;
    __syncthreads();
    {
        int gtid = blockIdx.x * 576 + tid;
        if (gtid < Pn) {
            int ai = aidx[gtid];
            int t1 = Z[pairs[2 * ai]];
            int t2 = Z[pairs[2 * ai + 1]];
            int tp = t1 * NT + t2;
            tpg[gtid] = (unsigned char)tp;
            atomicAdd(&loc[tp], 1);
        }
        for (int idx = gtid; idx < PERMCAP; idx += 100 * 576)
            permg[idx] = -1;
    }
    if (blockIdx.x == 0 && tid < NDS) {
        int e = tid;
        int t  = TBc.ds_t[e];
        int l1 = TBc.om_l1[t], l2 = TBc.om_l2[t], mn = TBc.om_mn[t];
        int klo = (l1 - l2) * (l1 - l2);
        int len = TBc.ds_len[e], off = TBc.ds_off[e];
        for (int q = 0; q < len; q++) {
            int k = klo + q;
            int l3 = (k < 1) ? 0 : (k < 4) ? 1 : (k < 9) ? 2 : (k < 16) ? 3 : 4;
            int ap = k - l3 * l3;
            Mg[off + q] = cgp.v[TBc.cgoff[l1][l2][l3] + mn * (2 * l3 + 1) + ap];
        }
    }
    __syncthreads();
    if (tid < 100 && loc[tid] > 0) atomicAdd(&cntg[tid], loc[tid]);
    if (tid >= 560) return;
    int tp = blockIdx.x;
    int t1 = tp / NT, t2 = tp % NT;
    int combo = tid >> 4, c = tid & 15;
    int xy = TBc.h_xy[combo], l3 = TBc.h_l3[combo];
    int x = TBc.tri_x[xy], y = TBc.tri_y[xy];
    const float* w1 = weight + (size_t)(t1 * NT + t2) * 1280 + l3 * 256;
    const float* w2 = weight + (size_t)(t2 * NT + t1) * 1280 + l3 * 256;
    float acc = 0.f;
    #pragma unroll
    for (int b = 0; b < 16; b++)
        acc += coll[x * 16 + b] * coll[y * 16 + b] * (w1[b * 16 + c] + w2[b * 16 + c]);
    Hg[(tp * 35 + combo) * 16 + c] = acc;
}

// ============================================================================
// Scan (reads cntg, writes fillg, re-zeroes cntg; bins padded to PPC)
// ============================================================================
__global__ void scan_kernel() {
    __shared__ int c_s[100];
    int tid = threadIdx.x;
    if (tid < 100) {
        c_s[tid] = cntg[tid];
        cntg[tid] = 0;
    }
    __syncthreads();
    if (tid == 0) {
        int run = 0;
        for (int b = 0; b < 100; b++) {
            int c = c_s[b];
            c_s[b] = run;
            run += (c + PPC - 1) & ~(PPC - 1);
        }
    }
    __syncthreads();
    if (tid < 100) fillg[tid] = c_s[tid];
}

__global__ void scatter_kernel(int Pn) {
    __shared__ int loc[100];
    __shared__ int base_s[100];
    int tid = threadIdx.x;
    if (tid < 100) loc[tid] = 0;
    __syncthreads();
    int p = blockIdx.x * blockDim.x + tid;
    int tp = -1, rank = 0;
    if (p < Pn) {
        tp = (int)tpg[p];
        rank = atomicAdd(&loc[tp], 1);
    }
    __syncthreads();
    if (tid < 100)
        base_s[tid] = (loc[tid] > 0) ? atomicAdd(&fillg[tid], loc[tid]) : 0;
    __syncthreads();
    if (p < Pn)
        permg[base_s[tp] + rank] = p;
}

// ============================================================================
// Main kernel: 2 pairs per warp (interleaved), 16 pairs/CTA, uniform tp.
// Per-warp dyn smem (floats):
//   EwpA[0,124)  EwpB[124,248)
//     rbfA overlays EwpA[0,32), gshA overlays EwpA[32,112)
//     rbfB overlays EwpB[0,32), gshB overlays EwpB[32,112)
//   cinA[248,673) cinB[673,1098)   (25 rows, stride 17)
// WSLOT=1100 -> dyn 35.2KB
// ============================================================================
#define WSLOT 1100

__global__ void __launch_bounds__(256, 4) op_kernel(
    const float* __restrict__ c0, const float* __restrict__ c1,
    const float* __restrict__ c2, const float* __restrict__ c3,
    const float* __restrict__ c4,
    const float* __restrict__ Rpos, const float* __restrict__ w_rad,
    const int* __restrict__ pairs,
    float* __restrict__ out)
{
    __shared__ __align__(16) float Hs[35 * 17 + 5];
    __shared__ __align__(16) float Mv[MMAX];
    __shared__ unsigned int etp_s[121];     // combo<<16 | k<<8 | dst
    __shared__ unsigned int dsp_s[NDS];     // off<<12 | ew<<5 | len
    __shared__ unsigned int dst2_s[NDS];    // t<<16 | t2
    __shared__ int ctaTp;
    extern __shared__ __align__(16) float dyn[];

    int tid = threadIdx.x, w = tid >> 5, lane = tid & 31;
    int base = blockIdx.x * PPC;

    if (tid == 0) {
        int pe0 = permg[base];
        ctaTp = (pe0 >= 0) ? (int)tpg[pe0] : -1;
    }
    for (int idx = tid; idx < TBc.m_total; idx += 256) Mv[idx] = Mg[idx];
    if (tid < 121)
        etp_s[tid] = ((unsigned)TBc.et_combo[tid] << 16) |
                     ((unsigned)TBc.et_k[tid] << 8) |
                     (unsigned)TBc.et_dst[tid];
    if (tid < NDS) {
        dsp_s[tid] = ((unsigned)TBc.ds_off[tid] << 12) |
                     ((unsigned)TBc.ds_ew[tid] << 5) |
                     (unsigned)TBc.ds_len[tid];
        dst2_s[tid] = ((unsigned)TBc.ds_t[tid] << 16) |
                      (unsigned)TBc.ds_t2[tid];
    }
    __syncthreads();
    int tpc = ctaTp;
    if (tpc < 0) return;
    {
        const float* Hsrc = Hg + (size_t)tpc * 560;
        for (int idx = tid; idx < 560; idx += 256) {
            int combo = idx >> 4, c = idx & 15;
            Hs[combo * 17 + c] = Hsrc[idx];
        }
    }
    __syncthreads();

    int peA = permg[base + w];
    if (peA < 0) return;
    int peB = permg[base + 8 + w];
    if (peB < 0) peB = peA;   // duplicate work; same value written twice

    float* Wp   = dyn + w * WSLOT;
    float* EwpA = Wp;
    float* EwpB = Wp + 124;
    float* rbfA = EwpA;             // [0,32)
    float* rbfB = EwpB;
    float* gshA = EwpA + 32;        // [32,112)
    float* gshB = EwpB + 32;
    float* cinA = Wp + 248;
    float* cinB = Wp + 673;

    int iA = pairs[2 * peA], jA = pairs[2 * peA + 1];
    int iB = pairs[2 * peB], jB = pairs[2 * peB + 1];

    {
        float dxA = Rpos[3*iA+0] - Rpos[3*jA+0];
        float dyA = Rpos[3*iA+1] - Rpos[3*jA+1];
        float dzA = Rpos[3*iA+2] - Rpos[3*jA+2];
        float dA  = sqrtf(dxA*dxA + dyA*dyA + dzA*dzA);
        float envA = (dA < RCUTF) ? 0.5f * (cosf(PI_F * dA / RCUTF) + 1.0f) : 0.0f;
        rbfA[lane] = sinf((float)(lane + 1) * PI_F * dA / RCUTF) * envA;
        float dxB = Rpos[3*iB+0] - Rpos[3*jB+0];
        float dyB = Rpos[3*iB+1] - Rpos[3*jB+1];
        float dzB = Rpos[3*iB+2] - Rpos[3*jB+2];
        float dB  = sqrtf(dxB*dxB + dyB*dyB + dzB*dzB);
        float envB = (dB < RCUTF) ? 0.5f * (cosf(PI_F * dB / RCUTF) + 1.0f) : 0.0f;
        rbfB[lane] = sinf((float)(lane + 1) * PI_F * dB / RCUTF) * envB;
    }
    __syncwarp();

    int f = lane & 15, h = lane >> 4;

    // ---- Phase A (dual): one w_rad load feeds both pairs ----
    {
        const float4* rvA = (const float4*)rbfA;
        const float4* rvB = (const float4*)rbfB;
        int lbase = h ? 3 : 0;
        int nl = h ? 2 : 3;
        float a0A = 0.f, a1A = 0.f, a2A = 0.f;
        float a0B = 0.f, a1B = 0.f, a2B = 0.f;
        const float* wb = w_rad + lbase * 512 + f;
        #pragma unroll
        for (int q = 0; q < 8; q++) {
            float4 rA = rvA[q];
            float4 rB = rvB[q];
            const float* wl0 = wb + q * 64;
            float w00 = __ldg(wl0 +  0), w01 = __ldg(wl0 + 16);
            float w02 = __ldg(wl0 + 32), w03 = __ldg(wl0 + 48);
            a0A = fmaf(rA.x, w00, a0A); a0B = fmaf(rB.x, w00, a0B);
            a0A = fmaf(rA.y, w01, a0A); a0B = fmaf(rB.y, w01, a0B);
            a0A = fmaf(rA.z, w02, a0A); a0B = fmaf(rB.z, w02, a0B);
            a0A = fmaf(rA.w, w03, a0A); a0B = fmaf(rB.w, w03, a0B);
            const float* wl1 = wl0 + 512;
            float w10 = __ldg(wl1 +  0), w11 = __ldg(wl1 + 16);
            float w12 = __ldg(wl1 + 32), w13 = __ldg(wl1 + 48);
            a1A = fmaf(rA.x, w10, a1A); a1B = fmaf(rB.x, w10, a1B);
            a1A = fmaf(rA.y, w11, a1A); a1B = fmaf(rB.y, w11, a1B);
            a1A = fmaf(rA.z, w12, a1A); a1B = fmaf(rB.z, w12, a1B);
            a1A = fmaf(rA.w, w13, a1A); a1B = fmaf(rB.w, w13, a1B);
            if (nl > 2) {
                const float* wl2 = wl1 + 512;
                float w20 = __ldg(wl2 +  0), w21 = __ldg(wl2 + 16);
                float w22 = __ldg(wl2 + 32), w23 = __ldg(wl2 + 48);
                a2A = fmaf(rA.x, w20, a2A); a2B = fmaf(rB.x, w20, a2B);
                a2A = fmaf(rA.y, w21, a2A); a2B = fmaf(rB.y, w21, a2B);
                a2A = fmaf(rA.z, w22, a2A); a2B = fmaf(rB.z, w22, a2B);
                a2A = fmaf(rA.w, w23, a2A); a2B = fmaf(rB.w, w23, a2B);
            }
        }
        __syncwarp();   // all rbf reads complete before gsh writes same region?
                        // (disjoint: rbf [0,32), gsh [32,112)) — sync for warp order
        gshA[(lbase + 0) * 16 + f] = a0A;
        gshB[(lbase + 0) * 16 + f] = a0B;
        gshA[(lbase + 1) * 16 + f] = a1A;
        gshB[(lbase + 1) * 16 + f] = a1B;
        if (nl > 2) {
            gshA[(lbase + 2) * 16 + f] = a2A;
            gshB[(lbase + 2) * 16 + f] = a2B;
        }
    }
    __syncwarp();

    // ---- Stage cin (dual streams) ----
    {
        const float* clp[5] = {c0, c1, c2, c3, c4};
        #pragma unroll
        for (int l = 0; l < 5; l++) {
            const int nm = 2 * l + 1;
            const float* ciA = clp[l] + (size_t)iA * 16 * nm;
            const float* cjA = clp[l] + (size_t)jA * 16 * nm;
            const float* ciB = clp[l] + (size_t)iB * 16 * nm;
            const float* cjB = clp[l] + (size_t)jB * 16 * nm;
            for (int idx = lane; idx < 16 * nm; idx += 32) {
                int c = idx / nm, m = idx - c * nm;
                int dst = (l * l + m) * 17 + c;
                cinA[dst] = gshA[l * 16 + c] * (ciA[idx] + cjA[idx]);
                cinB[dst] = gshB[l * 16 + c] * (ciB[idx] + cjB[idx]);
            }
        }
    }
    __syncwarp();

    // ---- Phase C' (dual): one H row feeds both pairs; writes Ewp (gsh dead) --
    for (int e = lane; e < 121; e += 32) {
        unsigned pk = etp_s[e];
        int combo = pk >> 16, k = (pk >> 8) & 0xFF, dst = pk & 0xFF;
        const float* Hr = Hs + combo * 17;
        const float* crA = cinA + k * 17;
        const float* crB = cinB + k * 17;
        float accA = 0.f, accB = 0.f;
        #pragma unroll
        for (int c = 0; c < 16; c++) {
            float hv = Hr[c];
            accA = fmaf(hv, crA[c], accA);
            accB = fmaf(hv, crB[c], accB);
        }
        EwpA[dst] = accA;
        EwpB[dst] = accB;
    }
    __syncwarp();

    // ---- Phase D (dual, deduped): 133 unique entries, mirror writes ----
    float* opA = out + (size_t)peA * 196;
    float* opB = out + (size_t)peB * 196;
    for (int e = lane; e < NDS; e += 32) {
        unsigned pk = dsp_s[e];
        int off = (pk >> 12) & 0xFFF, ew = (pk >> 5) & 0x7F, len = pk & 0x1F;
        unsigned tt = dst2_s[e];
        int t = tt >> 16, t2 = tt & 0xFFFF;
        const float* Mr = Mv + off;
        const float* ErA = EwpA + ew;
        const float* ErB = EwpB + ew;
        float accA = 0.f, accB = 0.f;
        for (int q = 0; q < len; q++) {
            float mv = Mr[q];
            accA = fmaf(mv, ErA[q], accA);
            accB = fmaf(mv, ErB[q], accB);
        }
        opA[t] = accA;
        opB[t] = accB;
        if (t2 != t) {
            opA[t2] = accA;
            opB[t2] = accB;
        }
    }
}

// ============================================================================
// Launch
// ============================================================================
extern "C" void kernel_launch(void* const* d_in, const int* in_sizes, int n_in,
                              void* d_out, int out_size) {
    const float* c0    = (const float*)d_in[0];
    const float* c1    = (const float*)d_in[1];
    const float* c2    = (const float*)d_in[2];
    const float* c3    = (const float*)d_in[3];
    const float* c4    = (const float*)d_in[4];
    const float* Rpos  = (const float*)d_in[5];
    const float* w_rad = (const float*)d_in[6];
    const float* wgt   = (const float*)d_in[7];
    const float* s_col = (const float*)d_in[8];
    const float* p_col = (const float*)d_in[9];
    const float* d_col = (const float*)d_in[10];
    const int*   Z     = (const int*)d_in[11];
    const int*   pairs = (const int*)d_in[12];
    const int*   aidx  = (const int*)d_in[13];
    float* out = (float*)d_out;

    int Pn = in_sizes[13];

    CGParam cg;
    fill_cg(cg.v);

    h_kernel<<<100, 576>>>(wgt, s_col, p_col, d_col, Z, pairs, aidx, Pn, cg);
    scan_kernel<<<1, 128>>>();
    scatter_kernel<<<(Pn + 255) / 256, 256>>>(Pn);

    size_t shmem = (size_t)WARPS * WSLOT * sizeof(float);
    cudaFuncSetAttribute(op_kernel, cudaFuncAttributeMaxDynamicSharedMemorySize, (int)shmem);
    int gridMain = (Pn + 100 * PPC + PPC - 1) / PPC;
    op_kernel<<<gridMain, 256, shmem>>>(c0, c1, c2, c3, c4, Rpos, w_rad,
                                        pairs, out);
}